// round 1
// baseline (speedup 1.0000x reference)
#include <cuda_runtime.h>
#include <math.h>

#define BATCH  2
#define SEQ    2048
#define HIDDEN 2048
#define NH     32
#define NKV    8
#define HD     64
#define KVDIM  (NKV*HD)   // 512

// Scratch (device globals — allocation-free)
__device__ float g_Q [BATCH*SEQ*HIDDEN];
__device__ float g_K [BATCH*SEQ*KVDIM];
__device__ float g_V [BATCH*SEQ*KVDIM];
__device__ float g_AO[BATCH*SEQ*HIDDEN];

// ---------------------------------------------------------------------------
// C[M,N] = A[M,K] @ B[N,K]^T   (row-major A, row-major B = weight, nn.Linear)
// 128x128 tile, BK=16, 256 threads, 8x8 per thread.
// ---------------------------------------------------------------------------
__global__ __launch_bounds__(256) void sgemm_nt(const float* __restrict__ A,
                                                const float* __restrict__ B,
                                                float* __restrict__ C,
                                                int M, int N, int K) {
    const int BM = 128, BN = 128, BK = 16;
    const int LDS_A = BM + 4;   // padded stride
    __shared__ float As[BK * (BM + 4)];
    __shared__ float Bs[BK * (BN + 4)];

    const int tid = threadIdx.x;
    const int tx  = tid & 15;
    const int ty  = tid >> 4;
    const int m0  = blockIdx.y * BM;
    const int n0  = blockIdx.x * BN;

    const int lr = tid >> 2;          // 0..63
    const int lc = (tid & 3) * 4;     // 0,4,8,12

    const float* Aptr = A + (size_t)(m0 + lr) * K + lc;
    const float* Bptr = B + (size_t)(n0 + lr) * K + lc;

    float acc[8][8];
#pragma unroll
    for (int i = 0; i < 8; i++)
#pragma unroll
        for (int j = 0; j < 8; j++) acc[i][j] = 0.0f;

    for (int k0 = 0; k0 < K; k0 += BK) {
        float4 a0 = *(const float4*)(Aptr + k0);
        float4 a1 = *(const float4*)(Aptr + (size_t)64 * K + k0);
        float4 b0 = *(const float4*)(Bptr + k0);
        float4 b1 = *(const float4*)(Bptr + (size_t)64 * K + k0);

        __syncthreads();   // previous iteration's reads complete
        As[(lc+0)*LDS_A + lr]      = a0.x;
        As[(lc+1)*LDS_A + lr]      = a0.y;
        As[(lc+2)*LDS_A + lr]      = a0.z;
        As[(lc+3)*LDS_A + lr]      = a0.w;
        As[(lc+0)*LDS_A + lr + 64] = a1.x;
        As[(lc+1)*LDS_A + lr + 64] = a1.y;
        As[(lc+2)*LDS_A + lr + 64] = a1.z;
        As[(lc+3)*LDS_A + lr + 64] = a1.w;

        Bs[(lc+0)*LDS_A + lr]      = b0.x;
        Bs[(lc+1)*LDS_A + lr]      = b0.y;
        Bs[(lc+2)*LDS_A + lr]      = b0.z;
        Bs[(lc+3)*LDS_A + lr]      = b0.w;
        Bs[(lc+0)*LDS_A + lr + 64] = b1.x;
        Bs[(lc+1)*LDS_A + lr + 64] = b1.y;
        Bs[(lc+2)*LDS_A + lr + 64] = b1.z;
        Bs[(lc+3)*LDS_A + lr + 64] = b1.w;
        __syncthreads();

#pragma unroll
        for (int k = 0; k < BK; k++) {
            float4 ra0 = *(const float4*)&As[k*LDS_A + ty*8];
            float4 ra1 = *(const float4*)&As[k*LDS_A + ty*8 + 4];
            float4 rb0 = *(const float4*)&Bs[k*LDS_A + tx*8];
            float4 rb1 = *(const float4*)&Bs[k*LDS_A + tx*8 + 4];
            float ra[8] = {ra0.x, ra0.y, ra0.z, ra0.w, ra1.x, ra1.y, ra1.z, ra1.w};
            float rb[8] = {rb0.x, rb0.y, rb0.z, rb0.w, rb1.x, rb1.y, rb1.z, rb1.w};
#pragma unroll
            for (int i = 0; i < 8; i++)
#pragma unroll
                for (int j = 0; j < 8; j++)
                    acc[i][j] = fmaf(ra[i], rb[j], acc[i][j]);
        }
    }

#pragma unroll
    for (int i = 0; i < 8; i++) {
        float* cptr = C + (size_t)(m0 + ty*8 + i) * N + n0 + tx*8;
        float4 c0 = make_float4(acc[i][0], acc[i][1], acc[i][2], acc[i][3]);
        float4 c1 = make_float4(acc[i][4], acc[i][5], acc[i][6], acc[i][7]);
        *(float4*)cptr       = c0;
        *(float4*)(cptr + 4) = c1;
    }
}

// ---------------------------------------------------------------------------
// Flash attention (causal, GQA). One CTA per (q-block of 64, head, batch).
// Q/K staged transposed [d][token] so inner GEMM loops read contiguous frags.
// 256 threads, each computes a 4x4 fragment of S and O.
// ---------------------------------------------------------------------------
#define BQ  64
#define BKT 64
#define LQ  68   // padded stride for Qst/Kst/Vs
#define LP  65   // padded stride for Pst

#define FLASH_SMEM ((3 * BKT * LQ + BKT * LP) * (int)sizeof(float))

__global__ __launch_bounds__(256) void flash_attn(const float* __restrict__ Q,
                                                  const float* __restrict__ Kg,
                                                  const float* __restrict__ Vg,
                                                  float* __restrict__ O) {
    extern __shared__ float sm[];
    float* Qst = sm;                 // [HD][BQ]  stride LQ
    float* Kst = Qst + BKT * LQ;     // [HD][BKT] stride LQ
    float* Vs  = Kst + BKT * LQ;     // [BKT][HD] stride LQ
    float* Pst = Vs  + BKT * LQ;     // [BKT][BQ] stride LP

    const int qb  = blockIdx.x;      // 0..31
    const int h   = blockIdx.y;      // 0..31
    const int b   = blockIdx.z;      // 0..1
    const int kvh = h >> 2;

    const int tid = threadIdx.x;
    const int tx  = tid & 15;
    const int ty  = tid >> 4;

    const int lr = tid >> 2;         // 0..63 token within tile
    const int lc = (tid & 3) * 4;    // 0,4,8,12 — d base; +u*16 covers 64

    // Load Q tile transposed, pre-scaled by 1/sqrt(64)
    {
        const float* qbase = Q + ((size_t)(b*SEQ + qb*BQ + lr)) * HIDDEN + h*HD;
#pragma unroll
        for (int u = 0; u < 4; u++) {
            int d = lc + u*16;
            float4 v = *(const float4*)(qbase + d);
            Qst[(d+0)*LQ + lr] = v.x * 0.125f;
            Qst[(d+1)*LQ + lr] = v.y * 0.125f;
            Qst[(d+2)*LQ + lr] = v.z * 0.125f;
            Qst[(d+3)*LQ + lr] = v.w * 0.125f;
        }
    }

    float m_i[4], l_i[4], acc[4][4];
#pragma unroll
    for (int i = 0; i < 4; i++) {
        m_i[i] = -1e30f;
        l_i[i] = 0.0f;
#pragma unroll
        for (int j = 0; j < 4; j++) acc[i][j] = 0.0f;
    }

    for (int kb = 0; kb <= qb; kb++) {
        __syncthreads();   // prev PV GEMM done reading Vs/Pst

        // Load K tile transposed + V tile
        {
            const float* kptr = Kg + ((size_t)(b*SEQ + kb*BKT + lr)) * KVDIM + kvh*HD;
            const float* vptr = Vg + ((size_t)(b*SEQ + kb*BKT + lr)) * KVDIM + kvh*HD;
#pragma unroll
            for (int u = 0; u < 4; u++) {
                int d = lc + u*16;
                float4 kv = *(const float4*)(kptr + d);
                Kst[(d+0)*LQ + lr] = kv.x;
                Kst[(d+1)*LQ + lr] = kv.y;
                Kst[(d+2)*LQ + lr] = kv.z;
                Kst[(d+3)*LQ + lr] = kv.w;
                float4 vv = *(const float4*)(vptr + d);
                *(float4*)&Vs[lr*LQ + d] = vv;
            }
        }
        __syncthreads();

        // S = Q @ K^T (pre-scaled)
        float s[4][4];
#pragma unroll
        for (int i = 0; i < 4; i++)
#pragma unroll
            for (int j = 0; j < 4; j++) s[i][j] = 0.0f;

#pragma unroll 8
        for (int d = 0; d < HD; d++) {
            float4 ra = *(const float4*)&Qst[d*LQ + ty*4];
            float4 rb = *(const float4*)&Kst[d*LQ + tx*4];
            float raf[4] = {ra.x, ra.y, ra.z, ra.w};
            float rbf[4] = {rb.x, rb.y, rb.z, rb.w};
#pragma unroll
            for (int i = 0; i < 4; i++)
#pragma unroll
                for (int j = 0; j < 4; j++)
                    s[i][j] = fmaf(raf[i], rbf[j], s[i][j]);
        }

        // Causal mask on diagonal tile
        if (kb == qb) {
#pragma unroll
            for (int i = 0; i < 4; i++)
#pragma unroll
                for (int j = 0; j < 4; j++)
                    if (tx*4 + j > ty*4 + i) s[i][j] = -1e30f;
        }

        // Online softmax (row reductions across the 16 tx lanes)
#pragma unroll
        for (int i = 0; i < 4; i++) {
            float mx = fmaxf(fmaxf(s[i][0], s[i][1]), fmaxf(s[i][2], s[i][3]));
#pragma unroll
            for (int o = 8; o >= 1; o >>= 1)
                mx = fmaxf(mx, __shfl_xor_sync(0xffffffffu, mx, o));
            float mnew  = fmaxf(m_i[i], mx);
            float alpha = __expf(m_i[i] - mnew);
            float p0 = __expf(s[i][0] - mnew);
            float p1 = __expf(s[i][1] - mnew);
            float p2 = __expf(s[i][2] - mnew);
            float p3 = __expf(s[i][3] - mnew);
            float rs = p0 + p1 + p2 + p3;
#pragma unroll
            for (int o = 8; o >= 1; o >>= 1)
                rs += __shfl_xor_sync(0xffffffffu, rs, o);
            l_i[i] = l_i[i] * alpha + rs;
            m_i[i] = mnew;
#pragma unroll
            for (int j = 0; j < 4; j++) acc[i][j] *= alpha;
            // store P transposed: Pst[k][q]
            Pst[(tx*4+0)*LP + ty*4 + i] = p0;
            Pst[(tx*4+1)*LP + ty*4 + i] = p1;
            Pst[(tx*4+2)*LP + ty*4 + i] = p2;
            Pst[(tx*4+3)*LP + ty*4 + i] = p3;
        }
        __syncthreads();

        // O += P @ V
#pragma unroll 8
        for (int ki = 0; ki < BKT; ki++) {
            float ra[4];
#pragma unroll
            for (int i = 0; i < 4; i++) ra[i] = Pst[ki*LP + ty*4 + i];
            float4 rb = *(const float4*)&Vs[ki*LQ + tx*4];
            float rbf[4] = {rb.x, rb.y, rb.z, rb.w};
#pragma unroll
            for (int i = 0; i < 4; i++)
#pragma unroll
                for (int j = 0; j < 4; j++)
                    acc[i][j] = fmaf(ra[i], rbf[j], acc[i][j]);
        }
    }

    // Write O (head-major hidden layout)
#pragma unroll
    for (int i = 0; i < 4; i++) {
        float inv = 1.0f / l_i[i];
        float* optr = O + ((size_t)(b*SEQ + qb*BQ + ty*4 + i)) * HIDDEN + h*HD + tx*4;
        float4 o = make_float4(acc[i][0]*inv, acc[i][1]*inv, acc[i][2]*inv, acc[i][3]*inv);
        *(float4*)optr = o;
    }
}

// ---------------------------------------------------------------------------
extern "C" void kernel_launch(void* const* d_in, const int* in_sizes, int n_in,
                              void* d_out, int out_size) {
    const float* x  = (const float*)d_in[0];
    const float* Wq = (const float*)d_in[1];
    const float* Wk = (const float*)d_in[2];
    const float* Wv = (const float*)d_in[3];
    const float* Wo = (const float*)d_in[4];
    float* out = (float*)d_out;

    float *Qp, *Kp, *Vp, *AOp;
    cudaGetSymbolAddress((void**)&Qp,  g_Q);
    cudaGetSymbolAddress((void**)&Kp,  g_K);
    cudaGetSymbolAddress((void**)&Vp,  g_V);
    cudaGetSymbolAddress((void**)&AOp, g_AO);

    const int M = BATCH * SEQ;   // 4096 tokens

    // Projections
    {
        dim3 blk(256);
        dim3 gq(HIDDEN/128, M/128);
        sgemm_nt<<<gq, blk>>>(x, Wq, Qp, M, HIDDEN, HIDDEN);
        dim3 gk(KVDIM/128, M/128);
        sgemm_nt<<<gk, blk>>>(x, Wk, Kp, M, KVDIM, HIDDEN);
        sgemm_nt<<<gk, blk>>>(x, Wv, Vp, M, KVDIM, HIDDEN);
    }

    // Flash attention
    {
        static bool attr_set = false;   // idempotent attribute set (host-side, not work)
        cudaFuncSetAttribute(flash_attn, cudaFuncAttributeMaxDynamicSharedMemorySize,
                             FLASH_SMEM);
        (void)attr_set;
        dim3 blk(256);
        dim3 grid(SEQ/BQ, NH, BATCH);
        flash_attn<<<grid, blk, FLASH_SMEM>>>(Qp, Kp, Vp, AOp);
    }

    // Output projection
    {
        dim3 blk(256);
        dim3 go(HIDDEN/128, M/128);
        sgemm_nt<<<go, blk>>>(AOp, Wo, out, M, HIDDEN, HIDDEN);
    }
}

// round 2
// speedup vs baseline: 1.4767x; 1.4767x over previous
#include <cuda_runtime.h>
#include <cuda_bf16.h>
#include <math.h>

#define BATCH  2
#define SEQ    2048
#define HIDDEN 2048
#define NH     32
#define NKV    8
#define HD     64
#define KVDIM  (NKV*HD)   // 512
#define MTOK   (BATCH*SEQ) // 4096

// ------------------------- device scratch (no allocs) ----------------------
__device__ float g_Q [MTOK*HIDDEN];
__device__ float g_K [MTOK*KVDIM];
__device__ float g_V [MTOK*KVDIM];

__device__ __nv_bfloat16 g_xh [MTOK*HIDDEN];
__device__ __nv_bfloat16 g_xl [MTOK*HIDDEN];
__device__ __nv_bfloat16 g_Wqh[HIDDEN*HIDDEN];
__device__ __nv_bfloat16 g_Wql[HIDDEN*HIDDEN];
__device__ __nv_bfloat16 g_Wkh[KVDIM*HIDDEN];
__device__ __nv_bfloat16 g_Wkl[KVDIM*HIDDEN];
__device__ __nv_bfloat16 g_Wvh[KVDIM*HIDDEN];
__device__ __nv_bfloat16 g_Wvl[KVDIM*HIDDEN];
__device__ __nv_bfloat16 g_Woh[HIDDEN*HIDDEN];
__device__ __nv_bfloat16 g_Wol[HIDDEN*HIDDEN];
__device__ __nv_bfloat16 g_AOh[MTOK*HIDDEN];
__device__ __nv_bfloat16 g_AOl[MTOK*HIDDEN];

// ---------------------------------------------------------------------------
// fp32 -> bf16 (hi, lo) split, vectorized by 4
// ---------------------------------------------------------------------------
__global__ void split_f32(const float* __restrict__ s,
                          __nv_bfloat16* __restrict__ hi,
                          __nv_bfloat16* __restrict__ lo, int n4) {
    int i = blockIdx.x * blockDim.x + threadIdx.x;
    if (i >= n4) return;
    float4 v = ((const float4*)s)[i];
    __nv_bfloat162 h01 = __floats2bfloat162_rn(v.x, v.y);
    __nv_bfloat162 h23 = __floats2bfloat162_rn(v.z, v.w);
    float2 f01 = __bfloat1622float2(h01);
    float2 f23 = __bfloat1622float2(h23);
    __nv_bfloat162 l01 = __floats2bfloat162_rn(v.x - f01.x, v.y - f01.y);
    __nv_bfloat162 l23 = __floats2bfloat162_rn(v.z - f23.x, v.w - f23.y);
    ((__nv_bfloat162*)hi)[2*i]   = h01;
    ((__nv_bfloat162*)hi)[2*i+1] = h23;
    ((__nv_bfloat162*)lo)[2*i]   = l01;
    ((__nv_bfloat162*)lo)[2*i+1] = l23;
}

// ---------------------------------------------------------------------------
// C[M,N] = A @ B^T with split-bf16: A = Ah+Al, B = Bh+Bl (both [rows][K] bf16)
// C fp32. 128x128 tile, BK=32, 256 threads (8 warps, 2x4), warp tile 64x32.
// mma.sync.m16n8k16, 3 MMAs per logical tile (hh, hl, lh).
// ---------------------------------------------------------------------------
#define LDA 40   // padded bf16 row stride in smem (conflict-free frag loads)

__device__ __forceinline__ void mma_bf16(float c[4],
                                         unsigned a0, unsigned a1, unsigned a2, unsigned a3,
                                         unsigned b0, unsigned b1) {
    asm volatile(
        "mma.sync.aligned.m16n8k16.row.col.f32.bf16.bf16.f32 "
        "{%0,%1,%2,%3}, {%4,%5,%6,%7}, {%8,%9}, {%0,%1,%2,%3};\n"
        : "+f"(c[0]), "+f"(c[1]), "+f"(c[2]), "+f"(c[3])
        : "r"(a0), "r"(a1), "r"(a2), "r"(a3), "r"(b0), "r"(b1));
}

__global__ __launch_bounds__(256, 1) void gemm_bf16x3(
    const __nv_bfloat16* __restrict__ Ah, const __nv_bfloat16* __restrict__ Al,
    const __nv_bfloat16* __restrict__ Bh, const __nv_bfloat16* __restrict__ Bl,
    float* __restrict__ C, int M, int N, int K) {

    __shared__ __nv_bfloat16 sAh[128*LDA], sAl[128*LDA];
    __shared__ __nv_bfloat16 sBh[128*LDA], sBl[128*LDA];

    const int tid  = threadIdx.x;
    const int lane = tid & 31;
    const int wid  = tid >> 5;
    const int wm   = wid & 1;        // 0..1  -> 64 rows
    const int wn   = wid >> 1;       // 0..3  -> 32 cols
    const int g    = lane >> 2;      // 0..7
    const int t    = lane & 3;       // 0..3
    const int m0   = blockIdx.y * 128;
    const int n0   = blockIdx.x * 128;

    const int lr = tid >> 2;         // 0..63 row within 64-row pass
    const int lk = (tid & 3) * 8;    // 0,8,16,24 bf16 within BK=32

    const __nv_bfloat16* pAh = Ah + (size_t)(m0 + lr) * K + lk;
    const __nv_bfloat16* pAl = Al + (size_t)(m0 + lr) * K + lk;
    const __nv_bfloat16* pBh = Bh + (size_t)(n0 + lr) * K + lk;
    const __nv_bfloat16* pBl = Bl + (size_t)(n0 + lr) * K + lk;
    const size_t rowskip = (size_t)64 * K;

    float acc[4][4][4];
#pragma unroll
    for (int a = 0; a < 4; a++)
#pragma unroll
        for (int b = 0; b < 4; b++)
#pragma unroll
            for (int c = 0; c < 4; c++) acc[a][b][c] = 0.0f;

    uint4 rah0, rah1, ral0, ral1, rbh0, rbh1, rbl0, rbl1;

    // prefetch tile 0
    rah0 = *(const uint4*)(pAh);           rah1 = *(const uint4*)(pAh + rowskip);
    ral0 = *(const uint4*)(pAl);           ral1 = *(const uint4*)(pAl + rowskip);
    rbh0 = *(const uint4*)(pBh);           rbh1 = *(const uint4*)(pBh + rowskip);
    rbl0 = *(const uint4*)(pBl);           rbl1 = *(const uint4*)(pBl + rowskip);

    for (int k0 = 0; k0 < K; k0 += 32) {
        __syncthreads();   // previous compute done reading smem
        *(uint4*)&sAh[lr*LDA + lk]        = rah0;
        *(uint4*)&sAh[(lr+64)*LDA + lk]   = rah1;
        *(uint4*)&sAl[lr*LDA + lk]        = ral0;
        *(uint4*)&sAl[(lr+64)*LDA + lk]   = ral1;
        *(uint4*)&sBh[lr*LDA + lk]        = rbh0;
        *(uint4*)&sBh[(lr+64)*LDA + lk]   = rbh1;
        *(uint4*)&sBl[lr*LDA + lk]        = rbl0;
        *(uint4*)&sBl[(lr+64)*LDA + lk]   = rbl1;
        __syncthreads();

        if (k0 + 32 < K) {   // prefetch next tile (hidden behind MMA work)
            int kn = k0 + 32;
            rah0 = *(const uint4*)(pAh + kn);           rah1 = *(const uint4*)(pAh + rowskip + kn);
            ral0 = *(const uint4*)(pAl + kn);           ral1 = *(const uint4*)(pAl + rowskip + kn);
            rbh0 = *(const uint4*)(pBh + kn);           rbh1 = *(const uint4*)(pBh + rowskip + kn);
            rbl0 = *(const uint4*)(pBl + kn);           rbl1 = *(const uint4*)(pBl + rowskip + kn);
        }

#pragma unroll
        for (int ks = 0; ks < 2; ks++) {
            const int kb = ks * 16 + t * 2;
            unsigned ah[4][4], al[4][4], bh[4][2], bl[4][2];
#pragma unroll
            for (int mt = 0; mt < 4; mt++) {
                int r = wm * 64 + mt * 16 + g;
                ah[mt][0] = *(const unsigned*)&sAh[r*LDA + kb];
                ah[mt][1] = *(const unsigned*)&sAh[(r+8)*LDA + kb];
                ah[mt][2] = *(const unsigned*)&sAh[r*LDA + kb + 8];
                ah[mt][3] = *(const unsigned*)&sAh[(r+8)*LDA + kb + 8];
                al[mt][0] = *(const unsigned*)&sAl[r*LDA + kb];
                al[mt][1] = *(const unsigned*)&sAl[(r+8)*LDA + kb];
                al[mt][2] = *(const unsigned*)&sAl[r*LDA + kb + 8];
                al[mt][3] = *(const unsigned*)&sAl[(r+8)*LDA + kb + 8];
            }
#pragma unroll
            for (int nt = 0; nt < 4; nt++) {
                int r = wn * 32 + nt * 8 + g;
                bh[nt][0] = *(const unsigned*)&sBh[r*LDA + kb];
                bh[nt][1] = *(const unsigned*)&sBh[r*LDA + kb + 8];
                bl[nt][0] = *(const unsigned*)&sBl[r*LDA + kb];
                bl[nt][1] = *(const unsigned*)&sBl[r*LDA + kb + 8];
            }
#pragma unroll
            for (int mt = 0; mt < 4; mt++)
#pragma unroll
                for (int nt = 0; nt < 4; nt++) {
                    mma_bf16(acc[mt][nt], ah[mt][0], ah[mt][1], ah[mt][2], ah[mt][3],
                             bh[nt][0], bh[nt][1]);
                    mma_bf16(acc[mt][nt], ah[mt][0], ah[mt][1], ah[mt][2], ah[mt][3],
                             bl[nt][0], bl[nt][1]);
                    mma_bf16(acc[mt][nt], al[mt][0], al[mt][1], al[mt][2], al[mt][3],
                             bh[nt][0], bh[nt][1]);
                }
        }
    }

#pragma unroll
    for (int mt = 0; mt < 4; mt++)
#pragma unroll
        for (int nt = 0; nt < 4; nt++) {
            int r = m0 + wm * 64 + mt * 16 + g;
            int c = n0 + wn * 32 + nt * 8 + t * 2;
            *(float2*)&C[(size_t)r * N + c]       = make_float2(acc[mt][nt][0], acc[mt][nt][1]);
            *(float2*)&C[(size_t)(r + 8) * N + c] = make_float2(acc[mt][nt][2], acc[mt][nt][3]);
        }
}

// ---------------------------------------------------------------------------
// Flash attention (causal, GQA) — fp32 SIMT, unchanged except bf16 hi/lo
// epilogue for the output-projection GEMM.
// ---------------------------------------------------------------------------
#define BQ  64
#define BKT 64
#define LQ  68
#define LP  65
#define FLASH_SMEM ((3 * BKT * LQ + BKT * LP) * (int)sizeof(float))

__global__ __launch_bounds__(256) void flash_attn(const float* __restrict__ Q,
                                                  const float* __restrict__ Kg,
                                                  const float* __restrict__ Vg,
                                                  __nv_bfloat16* __restrict__ Oh,
                                                  __nv_bfloat16* __restrict__ Ol) {
    extern __shared__ float sm[];
    float* Qst = sm;
    float* Kst = Qst + BKT * LQ;
    float* Vs  = Kst + BKT * LQ;
    float* Pst = Vs  + BKT * LQ;

    const int qb  = blockIdx.x;
    const int h   = blockIdx.y;
    const int b   = blockIdx.z;
    const int kvh = h >> 2;

    const int tid = threadIdx.x;
    const int tx  = tid & 15;
    const int ty  = tid >> 4;

    const int lr = tid >> 2;
    const int lc = (tid & 3) * 4;

    {
        const float* qbase = Q + ((size_t)(b*SEQ + qb*BQ + lr)) * HIDDEN + h*HD;
#pragma unroll
        for (int u = 0; u < 4; u++) {
            int d = lc + u*16;
            float4 v = *(const float4*)(qbase + d);
            Qst[(d+0)*LQ + lr] = v.x * 0.125f;
            Qst[(d+1)*LQ + lr] = v.y * 0.125f;
            Qst[(d+2)*LQ + lr] = v.z * 0.125f;
            Qst[(d+3)*LQ + lr] = v.w * 0.125f;
        }
    }

    float m_i[4], l_i[4], acc[4][4];
#pragma unroll
    for (int i = 0; i < 4; i++) {
        m_i[i] = -1e30f; l_i[i] = 0.0f;
#pragma unroll
        for (int j = 0; j < 4; j++) acc[i][j] = 0.0f;
    }

    for (int kb = 0; kb <= qb; kb++) {
        __syncthreads();
        {
            const float* kptr = Kg + ((size_t)(b*SEQ + kb*BKT + lr)) * KVDIM + kvh*HD;
            const float* vptr = Vg + ((size_t)(b*SEQ + kb*BKT + lr)) * KVDIM + kvh*HD;
#pragma unroll
            for (int u = 0; u < 4; u++) {
                int d = lc + u*16;
                float4 kv = *(const float4*)(kptr + d);
                Kst[(d+0)*LQ + lr] = kv.x;
                Kst[(d+1)*LQ + lr] = kv.y;
                Kst[(d+2)*LQ + lr] = kv.z;
                Kst[(d+3)*LQ + lr] = kv.w;
                float4 vv = *(const float4*)(vptr + d);
                *(float4*)&Vs[lr*LQ + d] = vv;
            }
        }
        __syncthreads();

        float s[4][4];
#pragma unroll
        for (int i = 0; i < 4; i++)
#pragma unroll
            for (int j = 0; j < 4; j++) s[i][j] = 0.0f;

#pragma unroll 8
        for (int d = 0; d < HD; d++) {
            float4 ra = *(const float4*)&Qst[d*LQ + ty*4];
            float4 rb = *(const float4*)&Kst[d*LQ + tx*4];
            float raf[4] = {ra.x, ra.y, ra.z, ra.w};
            float rbf[4] = {rb.x, rb.y, rb.z, rb.w};
#pragma unroll
            for (int i = 0; i < 4; i++)
#pragma unroll
                for (int j = 0; j < 4; j++)
                    s[i][j] = fmaf(raf[i], rbf[j], s[i][j]);
        }

        if (kb == qb) {
#pragma unroll
            for (int i = 0; i < 4; i++)
#pragma unroll
                for (int j = 0; j < 4; j++)
                    if (tx*4 + j > ty*4 + i) s[i][j] = -1e30f;
        }

#pragma unroll
        for (int i = 0; i < 4; i++) {
            float mx = fmaxf(fmaxf(s[i][0], s[i][1]), fmaxf(s[i][2], s[i][3]));
#pragma unroll
            for (int o = 8; o >= 1; o >>= 1)
                mx = fmaxf(mx, __shfl_xor_sync(0xffffffffu, mx, o));
            float mnew  = fmaxf(m_i[i], mx);
            float alpha = __expf(m_i[i] - mnew);
            float p0 = __expf(s[i][0] - mnew);
            float p1 = __expf(s[i][1] - mnew);
            float p2 = __expf(s[i][2] - mnew);
            float p3 = __expf(s[i][3] - mnew);
            float rs = p0 + p1 + p2 + p3;
#pragma unroll
            for (int o = 8; o >= 1; o >>= 1)
                rs += __shfl_xor_sync(0xffffffffu, rs, o);
            l_i[i] = l_i[i] * alpha + rs;
            m_i[i] = mnew;
#pragma unroll
            for (int j = 0; j < 4; j++) acc[i][j] *= alpha;
            Pst[(tx*4+0)*LP + ty*4 + i] = p0;
            Pst[(tx*4+1)*LP + ty*4 + i] = p1;
            Pst[(tx*4+2)*LP + ty*4 + i] = p2;
            Pst[(tx*4+3)*LP + ty*4 + i] = p3;
        }
        __syncthreads();

#pragma unroll 8
        for (int ki = 0; ki < BKT; ki++) {
            float ra[4];
#pragma unroll
            for (int i = 0; i < 4; i++) ra[i] = Pst[ki*LP + ty*4 + i];
            float4 rb = *(const float4*)&Vs[ki*LQ + tx*4];
            float rbf[4] = {rb.x, rb.y, rb.z, rb.w};
#pragma unroll
            for (int i = 0; i < 4; i++)
#pragma unroll
                for (int j = 0; j < 4; j++)
                    acc[i][j] = fmaf(ra[i], rbf[j], acc[i][j]);
        }
    }

    // epilogue: split-bf16 write
#pragma unroll
    for (int i = 0; i < 4; i++) {
        float inv = 1.0f / l_i[i];
        float v0 = acc[i][0]*inv, v1 = acc[i][1]*inv, v2 = acc[i][2]*inv, v3 = acc[i][3]*inv;
        size_t off = ((size_t)(b*SEQ + qb*BQ + ty*4 + i)) * HIDDEN + h*HD + tx*4;
        __nv_bfloat162 h01 = __floats2bfloat162_rn(v0, v1);
        __nv_bfloat162 h23 = __floats2bfloat162_rn(v2, v3);
        float2 f01 = __bfloat1622float2(h01);
        float2 f23 = __bfloat1622float2(h23);
        __nv_bfloat162 l01 = __floats2bfloat162_rn(v0 - f01.x, v1 - f01.y);
        __nv_bfloat162 l23 = __floats2bfloat162_rn(v2 - f23.x, v3 - f23.y);
        *(uint2*)&Oh[off] = make_uint2(*(unsigned*)&h01, *(unsigned*)&h23);
        *(uint2*)&Ol[off] = make_uint2(*(unsigned*)&l01, *(unsigned*)&l23);
    }
}

// ---------------------------------------------------------------------------
extern "C" void kernel_launch(void* const* d_in, const int* in_sizes, int n_in,
                              void* d_out, int out_size) {
    const float* x  = (const float*)d_in[0];
    const float* Wq = (const float*)d_in[1];
    const float* Wk = (const float*)d_in[2];
    const float* Wv = (const float*)d_in[3];
    const float* Wo = (const float*)d_in[4];
    float* out = (float*)d_out;

    float *Qp, *Kp, *Vp;
    cudaGetSymbolAddress((void**)&Qp, g_Q);
    cudaGetSymbolAddress((void**)&Kp, g_K);
    cudaGetSymbolAddress((void**)&Vp, g_V);

    __nv_bfloat16 *xh, *xl, *wqh, *wql, *wkh, *wkl, *wvh, *wvl, *woh, *wol, *aoh, *aol;
    cudaGetSymbolAddress((void**)&xh,  g_xh);  cudaGetSymbolAddress((void**)&xl,  g_xl);
    cudaGetSymbolAddress((void**)&wqh, g_Wqh); cudaGetSymbolAddress((void**)&wql, g_Wql);
    cudaGetSymbolAddress((void**)&wkh, g_Wkh); cudaGetSymbolAddress((void**)&wkl, g_Wkl);
    cudaGetSymbolAddress((void**)&wvh, g_Wvh); cudaGetSymbolAddress((void**)&wvl, g_Wvl);
    cudaGetSymbolAddress((void**)&woh, g_Woh); cudaGetSymbolAddress((void**)&wol, g_Wol);
    cudaGetSymbolAddress((void**)&aoh, g_AOh); cudaGetSymbolAddress((void**)&aol, g_AOl);

    const int M = MTOK;

    // splits
    {
        int n4;
        n4 = M*HIDDEN/4;        split_f32<<<(n4+255)/256, 256>>>(x,  xh,  xl,  n4);
        n4 = HIDDEN*HIDDEN/4;   split_f32<<<(n4+255)/256, 256>>>(Wq, wqh, wql, n4);
        n4 = KVDIM*HIDDEN/4;    split_f32<<<(n4+255)/256, 256>>>(Wk, wkh, wkl, n4);
        n4 = KVDIM*HIDDEN/4;    split_f32<<<(n4+255)/256, 256>>>(Wv, wvh, wvl, n4);
        n4 = HIDDEN*HIDDEN/4;   split_f32<<<(n4+255)/256, 256>>>(Wo, woh, wol, n4);
    }

    // projections (tensor-core split-bf16)
    {
        dim3 blk(256);
        dim3 gq(HIDDEN/128, M/128);
        gemm_bf16x3<<<gq, blk>>>(xh, xl, wqh, wql, Qp, M, HIDDEN, HIDDEN);
        dim3 gk(KVDIM/128, M/128);
        gemm_bf16x3<<<gk, blk>>>(xh, xl, wkh, wkl, Kp, M, KVDIM, HIDDEN);
        gemm_bf16x3<<<gk, blk>>>(xh, xl, wvh, wvl, Vp, M, KVDIM, HIDDEN);
    }

    // flash attention
    {
        cudaFuncSetAttribute(flash_attn, cudaFuncAttributeMaxDynamicSharedMemorySize,
                             FLASH_SMEM);
        dim3 blk(256);
        dim3 grid(SEQ/BQ, NH, BATCH);
        flash_attn<<<grid, blk, FLASH_SMEM>>>(Qp, Kp, Vp, aoh, aol);
    }

    // output projection
    {
        dim3 blk(256);
        dim3 go(HIDDEN/128, M/128);
        gemm_bf16x3<<<go, blk>>>(aoh, aol, woh, wol, out, M, HIDDEN, HIDDEN);
    }
}

// round 3
// speedup vs baseline: 2.2188x; 1.5026x over previous
#include <cuda_runtime.h>
#include <cuda_bf16.h>
#include <math.h>

#define BATCH  2
#define SEQ    2048
#define HIDDEN 2048
#define NH     32
#define NKV    8
#define HD     64
#define KVDIM  (NKV*HD)   // 512
#define MTOK   (BATCH*SEQ) // 4096

// ------------------------- device scratch (no allocs) ----------------------
__device__ __nv_bfloat16 g_xh [MTOK*HIDDEN];
__device__ __nv_bfloat16 g_xl [MTOK*HIDDEN];
__device__ __nv_bfloat16 g_Wqh[HIDDEN*HIDDEN];
__device__ __nv_bfloat16 g_Wql[HIDDEN*HIDDEN];
__device__ __nv_bfloat16 g_Wkh[KVDIM*HIDDEN];
__device__ __nv_bfloat16 g_Wkl[KVDIM*HIDDEN];
__device__ __nv_bfloat16 g_Wvh[KVDIM*HIDDEN];
__device__ __nv_bfloat16 g_Wvl[KVDIM*HIDDEN];
__device__ __nv_bfloat16 g_Woh[HIDDEN*HIDDEN];
__device__ __nv_bfloat16 g_Wol[HIDDEN*HIDDEN];

__device__ __nv_bfloat16 g_Qh [MTOK*HIDDEN];
__device__ __nv_bfloat16 g_Ql [MTOK*HIDDEN];
__device__ __nv_bfloat16 g_Kh [MTOK*KVDIM];
__device__ __nv_bfloat16 g_Kl [MTOK*KVDIM];
__device__ __nv_bfloat16 g_Vh [MTOK*KVDIM];
__device__ __nv_bfloat16 g_Vl [MTOK*KVDIM];
__device__ __nv_bfloat16 g_Vth[BATCH*NKV*HD*SEQ];  // [(b*8+kvh)*64+d][token]
__device__ __nv_bfloat16 g_Vtl[BATCH*NKV*HD*SEQ];
__device__ __nv_bfloat16 g_AOh[MTOK*HIDDEN];
__device__ __nv_bfloat16 g_AOl[MTOK*HIDDEN];

// ---------------------------------------------------------------------------
__global__ void split_f32(const float* __restrict__ s,
                          __nv_bfloat16* __restrict__ hi,
                          __nv_bfloat16* __restrict__ lo, int n4) {
    int i = blockIdx.x * blockDim.x + threadIdx.x;
    if (i >= n4) return;
    float4 v = ((const float4*)s)[i];
    __nv_bfloat162 h01 = __floats2bfloat162_rn(v.x, v.y);
    __nv_bfloat162 h23 = __floats2bfloat162_rn(v.z, v.w);
    float2 f01 = __bfloat1622float2(h01);
    float2 f23 = __bfloat1622float2(h23);
    __nv_bfloat162 l01 = __floats2bfloat162_rn(v.x - f01.x, v.y - f01.y);
    __nv_bfloat162 l23 = __floats2bfloat162_rn(v.z - f23.x, v.w - f23.y);
    ((__nv_bfloat162*)hi)[2*i]   = h01;
    ((__nv_bfloat162*)hi)[2*i+1] = h23;
    ((__nv_bfloat162*)lo)[2*i]   = l01;
    ((__nv_bfloat162*)lo)[2*i+1] = l23;
}

// ---------------------------------------------------------------------------
__device__ __forceinline__ void mma_bf16(float c[4],
                                         unsigned a0, unsigned a1, unsigned a2, unsigned a3,
                                         unsigned b0, unsigned b1) {
    asm volatile(
        "mma.sync.aligned.m16n8k16.row.col.f32.bf16.bf16.f32 "
        "{%0,%1,%2,%3}, {%4,%5,%6,%7}, {%8,%9}, {%0,%1,%2,%3};\n"
        : "+f"(c[0]), "+f"(c[1]), "+f"(c[2]), "+f"(c[3])
        : "r"(a0), "r"(a1), "r"(a2), "r"(a3), "r"(b0), "r"(b1));
}

// ---------------------------------------------------------------------------
// Split-bf16 GEMM core: C = (Ah+Al)(Bh+Bl)^T, 128x128 tile, BK=32, 256 thr.
// Two epilogues: fp32 out (Wo) and bf16 hi/lo out with scale (Q/K/V).
// ---------------------------------------------------------------------------
#define LDA 40

#define GEMM_BODY                                                              \
    __shared__ __nv_bfloat16 sAh[128*LDA], sAl[128*LDA];                       \
    __shared__ __nv_bfloat16 sBh[128*LDA], sBl[128*LDA];                       \
    const int tid  = threadIdx.x;                                              \
    const int lane = tid & 31;                                                 \
    const int wid  = tid >> 5;                                                 \
    const int wm   = wid & 1;                                                  \
    const int wn   = wid >> 1;                                                 \
    const int g    = lane >> 2;                                                \
    const int t    = lane & 3;                                                 \
    const int m0   = blockIdx.y * 128;                                         \
    const int n0   = blockIdx.x * 128;                                         \
    const int lr = tid >> 2;                                                   \
    const int lk = (tid & 3) * 8;                                              \
    const __nv_bfloat16* pAh = Ah + (size_t)(m0 + lr) * K + lk;                \
    const __nv_bfloat16* pAl = Al + (size_t)(m0 + lr) * K + lk;                \
    const __nv_bfloat16* pBh = Bh + (size_t)(n0 + lr) * K + lk;                \
    const __nv_bfloat16* pBl = Bl + (size_t)(n0 + lr) * K + lk;                \
    const size_t rowskip = (size_t)64 * K;                                     \
    float acc[4][4][4];                                                        \
    _Pragma("unroll") for (int a = 0; a < 4; a++)                              \
    _Pragma("unroll") for (int b = 0; b < 4; b++)                              \
    _Pragma("unroll") for (int c = 0; c < 4; c++) acc[a][b][c] = 0.0f;         \
    uint4 rah0, rah1, ral0, ral1, rbh0, rbh1, rbl0, rbl1;                      \
    rah0 = *(const uint4*)(pAh);           rah1 = *(const uint4*)(pAh + rowskip); \
    ral0 = *(const uint4*)(pAl);           ral1 = *(const uint4*)(pAl + rowskip); \
    rbh0 = *(const uint4*)(pBh);           rbh1 = *(const uint4*)(pBh + rowskip); \
    rbl0 = *(const uint4*)(pBl);           rbl1 = *(const uint4*)(pBl + rowskip); \
    for (int k0 = 0; k0 < K; k0 += 32) {                                       \
        __syncthreads();                                                       \
        *(uint4*)&sAh[lr*LDA + lk]        = rah0;                              \
        *(uint4*)&sAh[(lr+64)*LDA + lk]   = rah1;                              \
        *(uint4*)&sAl[lr*LDA + lk]        = ral0;                              \
        *(uint4*)&sAl[(lr+64)*LDA + lk]   = ral1;                              \
        *(uint4*)&sBh[lr*LDA + lk]        = rbh0;                              \
        *(uint4*)&sBh[(lr+64)*LDA + lk]   = rbh1;                              \
        *(uint4*)&sBl[lr*LDA + lk]        = rbl0;                              \
        *(uint4*)&sBl[(lr+64)*LDA + lk]   = rbl1;                              \
        __syncthreads();                                                       \
        if (k0 + 32 < K) {                                                     \
            int kn = k0 + 32;                                                  \
            rah0 = *(const uint4*)(pAh + kn); rah1 = *(const uint4*)(pAh + rowskip + kn); \
            ral0 = *(const uint4*)(pAl + kn); ral1 = *(const uint4*)(pAl + rowskip + kn); \
            rbh0 = *(const uint4*)(pBh + kn); rbh1 = *(const uint4*)(pBh + rowskip + kn); \
            rbl0 = *(const uint4*)(pBl + kn); rbl1 = *(const uint4*)(pBl + rowskip + kn); \
        }                                                                      \
        _Pragma("unroll")                                                      \
        for (int ks = 0; ks < 2; ks++) {                                       \
            const int kb = ks * 16 + t * 2;                                    \
            unsigned ah[4][4], al[4][4], bh[4][2], bl[4][2];                   \
            _Pragma("unroll") for (int mt = 0; mt < 4; mt++) {                 \
                int r = wm * 64 + mt * 16 + g;                                 \
                ah[mt][0] = *(const unsigned*)&sAh[r*LDA + kb];                \
                ah[mt][1] = *(const unsigned*)&sAh[(r+8)*LDA + kb];            \
                ah[mt][2] = *(const unsigned*)&sAh[r*LDA + kb + 8];            \
                ah[mt][3] = *(const unsigned*)&sAh[(r+8)*LDA + kb + 8];        \
                al[mt][0] = *(const unsigned*)&sAl[r*LDA + kb];                \
                al[mt][1] = *(const unsigned*)&sAl[(r+8)*LDA + kb];            \
                al[mt][2] = *(const unsigned*)&sAl[r*LDA + kb + 8];            \
                al[mt][3] = *(const unsigned*)&sAl[(r+8)*LDA + kb + 8];        \
            }                                                                  \
            _Pragma("unroll") for (int nt = 0; nt < 4; nt++) {                 \
                int r = wn * 32 + nt * 8 + g;                                  \
                bh[nt][0] = *(const unsigned*)&sBh[r*LDA + kb];                \
                bh[nt][1] = *(const unsigned*)&sBh[r*LDA + kb + 8];            \
                bl[nt][0] = *(const unsigned*)&sBl[r*LDA + kb];                \
                bl[nt][1] = *(const unsigned*)&sBl[r*LDA + kb + 8];            \
            }                                                                  \
            _Pragma("unroll") for (int mt = 0; mt < 4; mt++)                   \
            _Pragma("unroll") for (int nt = 0; nt < 4; nt++) {                 \
                mma_bf16(acc[mt][nt], ah[mt][0], ah[mt][1], ah[mt][2], ah[mt][3], \
                         bh[nt][0], bh[nt][1]);                                \
                mma_bf16(acc[mt][nt], ah[mt][0], ah[mt][1], ah[mt][2], ah[mt][3], \
                         bl[nt][0], bl[nt][1]);                                \
                mma_bf16(acc[mt][nt], al[mt][0], al[mt][1], al[mt][2], al[mt][3], \
                         bh[nt][0], bh[nt][1]);                                \
            }                                                                  \
        }                                                                      \
    }

__global__ __launch_bounds__(256, 1) void gemm_bf16x3_f32out(
    const __nv_bfloat16* __restrict__ Ah, const __nv_bfloat16* __restrict__ Al,
    const __nv_bfloat16* __restrict__ Bh, const __nv_bfloat16* __restrict__ Bl,
    float* __restrict__ C, int M, int N, int K) {
    GEMM_BODY
#pragma unroll
    for (int mt = 0; mt < 4; mt++)
#pragma unroll
        for (int nt = 0; nt < 4; nt++) {
            int r = m0 + wm * 64 + mt * 16 + g;
            int c = n0 + wn * 32 + nt * 8 + t * 2;
            *(float2*)&C[(size_t)r * N + c]       = make_float2(acc[mt][nt][0], acc[mt][nt][1]);
            *(float2*)&C[(size_t)(r + 8) * N + c] = make_float2(acc[mt][nt][2], acc[mt][nt][3]);
        }
}

__global__ __launch_bounds__(256, 1) void gemm_bf16x3_bf16out(
    const __nv_bfloat16* __restrict__ Ah, const __nv_bfloat16* __restrict__ Al,
    const __nv_bfloat16* __restrict__ Bh, const __nv_bfloat16* __restrict__ Bl,
    __nv_bfloat16* __restrict__ Ch, __nv_bfloat16* __restrict__ Cl,
    int M, int N, int K, float scale) {
    GEMM_BODY
#pragma unroll
    for (int mt = 0; mt < 4; mt++)
#pragma unroll
        for (int nt = 0; nt < 4; nt++) {
            int r = m0 + wm * 64 + mt * 16 + g;
            int c = n0 + wn * 32 + nt * 8 + t * 2;
#pragma unroll
            for (int half = 0; half < 2; half++) {
                float v0 = acc[mt][nt][2*half+0] * scale;
                float v1 = acc[mt][nt][2*half+1] * scale;
                __nv_bfloat162 h = __floats2bfloat162_rn(v0, v1);
                float2 f = __bfloat1622float2(h);
                __nv_bfloat162 l = __floats2bfloat162_rn(v0 - f.x, v1 - f.y);
                size_t off = (size_t)(r + 8*half) * N + c;
                *(unsigned*)&Ch[off] = *(unsigned*)&h;
                *(unsigned*)&Cl[off] = *(unsigned*)&l;
            }
        }
}

// ---------------------------------------------------------------------------
// Transpose V: [token][kvh*64+d] -> [(b*8+kvh)*64+d][token]  (bf16, h & l)
// Block: one (b, kvh, 64-token stile); 128 threads.
// ---------------------------------------------------------------------------
__global__ __launch_bounds__(128) void transpose_v(
    const __nv_bfloat16* __restrict__ Vh, const __nv_bfloat16* __restrict__ Vl,
    __nv_bfloat16* __restrict__ Vth, __nv_bfloat16* __restrict__ Vtl) {
    __shared__ __nv_bfloat16 sm[64*72];
    const int st  = blockIdx.x;   // 0..31 token tile
    const int kvh = blockIdx.y;   // 0..7
    const int b   = blockIdx.z;   // 0..1
    const int tid = threadIdx.x;

    const __nv_bfloat16* src[2] = {Vh, Vl};
    __nv_bfloat16*       dst[2] = {Vth, Vtl};

#pragma unroll
    for (int a = 0; a < 2; a++) {
        __syncthreads();
        // load 64 tokens x 64 dims (uint4 = 8 dims)
#pragma unroll
        for (int i = 0; i < 4; i++) {
            int u = i*128 + tid;           // 0..511
            int r = u >> 3, c8 = u & 7;
            uint4 v = *(const uint4*)&src[a][((size_t)(b*SEQ + st*64 + r))*KVDIM + kvh*HD + c8*8];
            *(uint4*)&sm[r*72 + c8*8] = v;
        }
        __syncthreads();
        // write transposed: row d, 8 consecutive tokens per uint4
#pragma unroll
        for (int i = 0; i < 4; i++) {
            int u = i*128 + tid;
            int d = u >> 3, t8 = (u & 7) * 8;
            __nv_bfloat16 tmp[8];
#pragma unroll
            for (int j = 0; j < 8; j++) tmp[j] = sm[(t8+j)*72 + d];
            *(uint4*)&dst[a][((size_t)((b*NKV + kvh)*HD + d))*SEQ + st*64 + t8] = *(uint4*)tmp;
        }
    }
}

// ---------------------------------------------------------------------------
// Tensor-core flash attention (causal, GQA), split-bf16, register-resident P.
// CTA: 128 threads (4 warps), BQ=64 (16 q rows/warp), K-tile 64.
// ---------------------------------------------------------------------------
#define LK 72

__global__ __launch_bounds__(128) void flash_mma(
    const __nv_bfloat16* __restrict__ Qh, const __nv_bfloat16* __restrict__ Ql,
    const __nv_bfloat16* __restrict__ Kh, const __nv_bfloat16* __restrict__ Kl,
    const __nv_bfloat16* __restrict__ Vth, const __nv_bfloat16* __restrict__ Vtl,
    __nv_bfloat16* __restrict__ Oh, __nv_bfloat16* __restrict__ Ol) {

    __shared__ __nv_bfloat16 sKh[64*LK], sKl[64*LK], sVh[64*LK], sVl[64*LK];

    const int qb  = blockIdx.x;      // 0..31
    const int h   = blockIdx.y;      // 0..31
    const int b   = blockIdx.z;      // 0..1
    const int kvh = h >> 2;

    const int tid  = threadIdx.x;
    const int wid  = tid >> 5;
    const int lane = tid & 31;
    const int g    = lane >> 2;
    const int t    = lane & 3;

    // --- Q fragments in registers (already scaled by 1/8 at projection) ---
    unsigned qh[4][4], ql[4][4];
    {
        const size_t row0 = (size_t)(b*SEQ + qb*64 + wid*16 + g) * HIDDEN + h*HD;
        const size_t row1 = row0 + (size_t)8 * HIDDEN;
#pragma unroll
        for (int ks = 0; ks < 4; ks++) {
            int c = ks*16 + t*2;
            qh[ks][0] = *(const unsigned*)&Qh[row0 + c];
            qh[ks][1] = *(const unsigned*)&Qh[row1 + c];
            qh[ks][2] = *(const unsigned*)&Qh[row0 + c + 8];
            qh[ks][3] = *(const unsigned*)&Qh[row1 + c + 8];
            ql[ks][0] = *(const unsigned*)&Ql[row0 + c];
            ql[ks][1] = *(const unsigned*)&Ql[row1 + c];
            ql[ks][2] = *(const unsigned*)&Ql[row0 + c + 8];
            ql[ks][3] = *(const unsigned*)&Ql[row1 + c + 8];
        }
    }

    float o[8][4];
#pragma unroll
    for (int j = 0; j < 8; j++)
#pragma unroll
        for (int c = 0; c < 4; c++) o[j][c] = 0.0f;
    float m0 = -1e30f, m1 = -1e30f, l0 = 0.0f, l1 = 0.0f;

    for (int kb = 0; kb <= qb; kb++) {
        __syncthreads();   // previous iteration's MMA reads complete
        // --- load K tile (row-major) and Vt tile (d-major), bf16 h/l ---
        {
            const size_t kbase = (size_t)(b*SEQ + kb*64) * KVDIM + kvh*HD;
            const size_t vbase = (size_t)((b*NKV + kvh)*HD) * SEQ + kb*64;
#pragma unroll
            for (int i = 0; i < 4; i++) {
                int u = i*128 + tid;        // 0..511
                int r = u >> 3, c8 = (u & 7) * 8;
                *(uint4*)&sKh[r*LK + c8] = *(const uint4*)&Kh[kbase + (size_t)r*KVDIM + c8];
                *(uint4*)&sKl[r*LK + c8] = *(const uint4*)&Kl[kbase + (size_t)r*KVDIM + c8];
                *(uint4*)&sVh[r*LK + c8] = *(const uint4*)&Vth[vbase + (size_t)r*SEQ + c8];
                *(uint4*)&sVl[r*LK + c8] = *(const uint4*)&Vtl[vbase + (size_t)r*SEQ + c8];
            }
        }
        __syncthreads();

        // --- S = Q K^T (3-term split) ---
        float s[8][4];
#pragma unroll
        for (int j = 0; j < 8; j++) {
            s[j][0] = 0.0f; s[j][1] = 0.0f; s[j][2] = 0.0f; s[j][3] = 0.0f;
            const int rb = (8*j + g)*LK + t*2;
#pragma unroll
            for (int ks = 0; ks < 4; ks++) {
                unsigned bh0 = *(const unsigned*)&sKh[rb + ks*16];
                unsigned bh1 = *(const unsigned*)&sKh[rb + ks*16 + 8];
                unsigned bl0 = *(const unsigned*)&sKl[rb + ks*16];
                unsigned bl1 = *(const unsigned*)&sKl[rb + ks*16 + 8];
                mma_bf16(s[j], qh[ks][0], qh[ks][1], qh[ks][2], qh[ks][3], bh0, bh1);
                mma_bf16(s[j], qh[ks][0], qh[ks][1], qh[ks][2], qh[ks][3], bl0, bl1);
                mma_bf16(s[j], ql[ks][0], ql[ks][1], ql[ks][2], ql[ks][3], bh0, bh1);
            }
        }

        // --- causal mask (diagonal tile only) ---
        if (kb == qb) {
            const int r0 = wid*16 + g, r1 = r0 + 8;
#pragma unroll
            for (int j = 0; j < 8; j++) {
                int c0 = 8*j + t*2, c1 = c0 + 1;
                if (c0 > r0) s[j][0] = -1e30f;
                if (c1 > r0) s[j][1] = -1e30f;
                if (c0 > r1) s[j][2] = -1e30f;
                if (c1 > r1) s[j][3] = -1e30f;
            }
        }

        // --- online softmax (rows g and g+8; reduce across t-quad) ---
        float mx0 = -1e30f, mx1 = -1e30f;
#pragma unroll
        for (int j = 0; j < 8; j++) {
            mx0 = fmaxf(mx0, fmaxf(s[j][0], s[j][1]));
            mx1 = fmaxf(mx1, fmaxf(s[j][2], s[j][3]));
        }
        mx0 = fmaxf(mx0, __shfl_xor_sync(0xffffffffu, mx0, 1));
        mx0 = fmaxf(mx0, __shfl_xor_sync(0xffffffffu, mx0, 2));
        mx1 = fmaxf(mx1, __shfl_xor_sync(0xffffffffu, mx1, 1));
        mx1 = fmaxf(mx1, __shfl_xor_sync(0xffffffffu, mx1, 2));
        float mn0 = fmaxf(m0, mx0), mn1 = fmaxf(m1, mx1);
        float al0 = __expf(m0 - mn0), al1 = __expf(m1 - mn1);

        float rs0 = 0.0f, rs1 = 0.0f;
#pragma unroll
        for (int j = 0; j < 8; j++) {
            s[j][0] = __expf(s[j][0] - mn0);
            s[j][1] = __expf(s[j][1] - mn0);
            s[j][2] = __expf(s[j][2] - mn1);
            s[j][3] = __expf(s[j][3] - mn1);
            rs0 += s[j][0] + s[j][1];
            rs1 += s[j][2] + s[j][3];
        }
        rs0 += __shfl_xor_sync(0xffffffffu, rs0, 1);
        rs0 += __shfl_xor_sync(0xffffffffu, rs0, 2);
        rs1 += __shfl_xor_sync(0xffffffffu, rs1, 1);
        rs1 += __shfl_xor_sync(0xffffffffu, rs1, 2);
        l0 = l0 * al0 + rs0;  m0 = mn0;
        l1 = l1 * al1 + rs1;  m1 = mn1;

#pragma unroll
        for (int j = 0; j < 8; j++) {
            o[j][0] *= al0; o[j][1] *= al0;
            o[j][2] *= al1; o[j][3] *= al1;
        }

        // --- pack P into bf16 h/l A-fragments (register-resident) ---
        unsigned ph[4][4], pl[4][4];
#pragma unroll
        for (int ks = 0; ks < 4; ks++) {
            __nv_bfloat162 h0 = __floats2bfloat162_rn(s[2*ks][0],   s[2*ks][1]);
            __nv_bfloat162 h1 = __floats2bfloat162_rn(s[2*ks][2],   s[2*ks][3]);
            __nv_bfloat162 h2 = __floats2bfloat162_rn(s[2*ks+1][0], s[2*ks+1][1]);
            __nv_bfloat162 h3 = __floats2bfloat162_rn(s[2*ks+1][2], s[2*ks+1][3]);
            float2 f0 = __bfloat1622float2(h0);
            float2 f1 = __bfloat1622float2(h1);
            float2 f2 = __bfloat1622float2(h2);
            float2 f3 = __bfloat1622float2(h3);
            __nv_bfloat162 L0 = __floats2bfloat162_rn(s[2*ks][0]-f0.x,   s[2*ks][1]-f0.y);
            __nv_bfloat162 L1 = __floats2bfloat162_rn(s[2*ks][2]-f1.x,   s[2*ks][3]-f1.y);
            __nv_bfloat162 L2 = __floats2bfloat162_rn(s[2*ks+1][0]-f2.x, s[2*ks+1][1]-f2.y);
            __nv_bfloat162 L3 = __floats2bfloat162_rn(s[2*ks+1][2]-f3.x, s[2*ks+1][3]-f3.y);
            ph[ks][0] = *(unsigned*)&h0; ph[ks][1] = *(unsigned*)&h1;
            ph[ks][2] = *(unsigned*)&h2; ph[ks][3] = *(unsigned*)&h3;
            pl[ks][0] = *(unsigned*)&L0; pl[ks][1] = *(unsigned*)&L1;
            pl[ks][2] = *(unsigned*)&L2; pl[ks][3] = *(unsigned*)&L3;
        }

        // --- O += P V (3-term split) ---
#pragma unroll
        for (int j = 0; j < 8; j++) {
            const int rb = (8*j + g)*LK + t*2;
#pragma unroll
            for (int ks = 0; ks < 4; ks++) {
                unsigned bh0 = *(const unsigned*)&sVh[rb + ks*16];
                unsigned bh1 = *(const unsigned*)&sVh[rb + ks*16 + 8];
                unsigned bl0 = *(const unsigned*)&sVl[rb + ks*16];
                unsigned bl1 = *(const unsigned*)&sVl[rb + ks*16 + 8];
                mma_bf16(o[j], ph[ks][0], ph[ks][1], ph[ks][2], ph[ks][3], bh0, bh1);
                mma_bf16(o[j], ph[ks][0], ph[ks][1], ph[ks][2], ph[ks][3], bl0, bl1);
                mma_bf16(o[j], pl[ks][0], pl[ks][1], pl[ks][2], pl[ks][3], bh0, bh1);
            }
        }
    }

    // --- epilogue: normalize, split to bf16 h/l, store ---
    const float inv0 = 1.0f / l0, inv1 = 1.0f / l1;
    const size_t row0 = (size_t)(b*SEQ + qb*64 + wid*16 + g) * HIDDEN + h*HD;
    const size_t row1 = row0 + (size_t)8 * HIDDEN;
#pragma unroll
    for (int j = 0; j < 8; j++) {
        int c = 8*j + t*2;
        float v0 = o[j][0]*inv0, v1 = o[j][1]*inv0;
        float v2 = o[j][2]*inv1, v3 = o[j][3]*inv1;
        __nv_bfloat162 h01 = __floats2bfloat162_rn(v0, v1);
        __nv_bfloat162 h23 = __floats2bfloat162_rn(v2, v3);
        float2 f01 = __bfloat1622float2(h01);
        float2 f23 = __bfloat1622float2(h23);
        __nv_bfloat162 l01 = __floats2bfloat162_rn(v0 - f01.x, v1 - f01.y);
        __nv_bfloat162 l23 = __floats2bfloat162_rn(v2 - f23.x, v3 - f23.y);
        *(unsigned*)&Oh[row0 + c] = *(unsigned*)&h01;
        *(unsigned*)&Oh[row1 + c] = *(unsigned*)&h23;
        *(unsigned*)&Ol[row0 + c] = *(unsigned*)&l01;
        *(unsigned*)&Ol[row1 + c] = *(unsigned*)&l23;
    }
}

// ---------------------------------------------------------------------------
extern "C" void kernel_launch(void* const* d_in, const int* in_sizes, int n_in,
                              void* d_out, int out_size) {
    const float* x  = (const float*)d_in[0];
    const float* Wq = (const float*)d_in[1];
    const float* Wk = (const float*)d_in[2];
    const float* Wv = (const float*)d_in[3];
    const float* Wo = (const float*)d_in[4];
    float* out = (float*)d_out;

    __nv_bfloat16 *xh, *xl, *wqh, *wql, *wkh, *wkl, *wvh, *wvl, *woh, *wol;
    __nv_bfloat16 *qh, *qlp, *kh, *kl, *vh, *vl, *vth, *vtl, *aoh, *aol;
    cudaGetSymbolAddress((void**)&xh,  g_xh);  cudaGetSymbolAddress((void**)&xl,  g_xl);
    cudaGetSymbolAddress((void**)&wqh, g_Wqh); cudaGetSymbolAddress((void**)&wql, g_Wql);
    cudaGetSymbolAddress((void**)&wkh, g_Wkh); cudaGetSymbolAddress((void**)&wkl, g_Wkl);
    cudaGetSymbolAddress((void**)&wvh, g_Wvh); cudaGetSymbolAddress((void**)&wvl, g_Wvl);
    cudaGetSymbolAddress((void**)&woh, g_Woh); cudaGetSymbolAddress((void**)&wol, g_Wol);
    cudaGetSymbolAddress((void**)&qh,  g_Qh);  cudaGetSymbolAddress((void**)&qlp, g_Ql);
    cudaGetSymbolAddress((void**)&kh,  g_Kh);  cudaGetSymbolAddress((void**)&kl,  g_Kl);
    cudaGetSymbolAddress((void**)&vh,  g_Vh);  cudaGetSymbolAddress((void**)&vl,  g_Vl);
    cudaGetSymbolAddress((void**)&vth, g_Vth); cudaGetSymbolAddress((void**)&vtl, g_Vtl);
    cudaGetSymbolAddress((void**)&aoh, g_AOh); cudaGetSymbolAddress((void**)&aol, g_AOl);

    const int M = MTOK;

    // splits
    {
        int n4;
        n4 = M*HIDDEN/4;        split_f32<<<(n4+255)/256, 256>>>(x,  xh,  xl,  n4);
        n4 = HIDDEN*HIDDEN/4;   split_f32<<<(n4+255)/256, 256>>>(Wq, wqh, wql, n4);
        n4 = KVDIM*HIDDEN/4;    split_f32<<<(n4+255)/256, 256>>>(Wk, wkh, wkl, n4);
        n4 = KVDIM*HIDDEN/4;    split_f32<<<(n4+255)/256, 256>>>(Wv, wvh, wvl, n4);
        n4 = HIDDEN*HIDDEN/4;   split_f32<<<(n4+255)/256, 256>>>(Wo, woh, wol, n4);
    }

    // projections -> bf16 h/l (Q pre-scaled by 1/8)
    {
        dim3 blk(256);
        dim3 gq(HIDDEN/128, M/128);
        gemm_bf16x3_bf16out<<<gq, blk>>>(xh, xl, wqh, wql, qh, qlp, M, HIDDEN, HIDDEN, 0.125f);
        dim3 gk(KVDIM/128, M/128);
        gemm_bf16x3_bf16out<<<gk, blk>>>(xh, xl, wkh, wkl, kh, kl, M, KVDIM, HIDDEN, 1.0f);
        gemm_bf16x3_bf16out<<<gk, blk>>>(xh, xl, wvh, wvl, vh, vl, M, KVDIM, HIDDEN, 1.0f);
    }

    // V transpose
    {
        dim3 grid(SEQ/64, NKV, BATCH);
        transpose_v<<<grid, 128>>>(vh, vl, vth, vtl);
    }

    // flash attention (tensor cores)
    {
        dim3 grid(SEQ/64, NH, BATCH);
        flash_mma<<<grid, 128>>>(qh, qlp, kh, kl, vth, vtl, aoh, aol);
    }

    // output projection (fp32 out)
    {
        dim3 blk(256);
        dim3 go(HIDDEN/128, M/128);
        gemm_bf16x3_f32out<<<go, blk>>>(aoh, aol, woh, wol, out, M, HIDDEN, HIDDEN);
    }
}

// round 5
// speedup vs baseline: 2.4471x; 1.1029x over previous
#include <cuda_runtime.h>
#include <cuda_bf16.h>
#include <math.h>
#include <stdint.h>

#define BATCH  2
#define SEQ    2048
#define HIDDEN 2048
#define NH     32
#define NKV    8
#define HD     64
#define KVDIM  (NKV*HD)    // 512
#define MTOK   (BATCH*SEQ) // 4096
#define QKVW   (HIDDEN + 2*KVDIM)  // 3072

// ------------------------- device scratch (no allocs) ----------------------
__device__ __nv_bfloat16 g_xh [MTOK*HIDDEN];
__device__ __nv_bfloat16 g_xl [MTOK*HIDDEN];
__device__ __nv_bfloat16 g_Wh [QKVW*HIDDEN];     // Wq | Wk | Wv rows concat
__device__ __nv_bfloat16 g_Wl [QKVW*HIDDEN];
__device__ __nv_bfloat16 g_Woh[HIDDEN*HIDDEN];
__device__ __nv_bfloat16 g_Wol[HIDDEN*HIDDEN];

__device__ __nv_bfloat16 g_QKVh[MTOK*QKVW];      // [token][ Q(2048) K(512) V(512) ]
__device__ __nv_bfloat16 g_QKVl[MTOK*QKVW];
__device__ __nv_bfloat16 g_Vth[BATCH*NKV*HD*SEQ];
__device__ __nv_bfloat16 g_Vtl[BATCH*NKV*HD*SEQ];
__device__ __nv_bfloat16 g_AOh[MTOK*HIDDEN];
__device__ __nv_bfloat16 g_AOl[MTOK*HIDDEN];

// ============================ helpers ======================================
__device__ __forceinline__ uint32_t smem_u32(const void* p) {
    uint32_t a;
    asm("{ .reg .u64 t; cvta.to.shared.u64 t, %1; cvt.u32.u64 %0, t; }"
        : "=r"(a) : "l"(p));
    return a;
}
__device__ __forceinline__ void cpa16(uint32_t dst, const void* src) {
    asm volatile("cp.async.cg.shared.global [%0], [%1], 16;\n" :: "r"(dst), "l"(src));
}
#define CPA_COMMIT() asm volatile("cp.async.commit_group;\n" ::: "memory")
#define CPA_WAIT_1() asm volatile("cp.async.wait_group 1;\n" ::: "memory")
#define CPA_WAIT_0() asm volatile("cp.async.wait_group 0;\n" ::: "memory")

__device__ __forceinline__ void mma_bf16(float c[4],
                                         unsigned a0, unsigned a1, unsigned a2, unsigned a3,
                                         unsigned b0, unsigned b1) {
    asm volatile(
        "mma.sync.aligned.m16n8k16.row.col.f32.bf16.bf16.f32 "
        "{%0,%1,%2,%3}, {%4,%5,%6,%7}, {%8,%9}, {%0,%1,%2,%3};\n"
        : "+f"(c[0]), "+f"(c[1]), "+f"(c[2]), "+f"(c[3])
        : "r"(a0), "r"(a1), "r"(a2), "r"(a3), "r"(b0), "r"(b1));
}
#define LDM4(r0, r1, r2, r3, a) \
    asm volatile("ldmatrix.sync.aligned.m8n8.x4.shared.b16 {%0,%1,%2,%3}, [%4];" \
        : "=r"(r0), "=r"(r1), "=r"(r2), "=r"(r3) : "r"(a))

// ---------------------------------------------------------------------------
__global__ void split_f32(const float* __restrict__ s,
                          __nv_bfloat16* __restrict__ hi,
                          __nv_bfloat16* __restrict__ lo, int n4) {
    int i = blockIdx.x * blockDim.x + threadIdx.x;
    if (i >= n4) return;
    float4 v = ((const float4*)s)[i];
    __nv_bfloat162 h01 = __floats2bfloat162_rn(v.x, v.y);
    __nv_bfloat162 h23 = __floats2bfloat162_rn(v.z, v.w);
    float2 f01 = __bfloat1622float2(h01);
    float2 f23 = __bfloat1622float2(h23);
    __nv_bfloat162 l01 = __floats2bfloat162_rn(v.x - f01.x, v.y - f01.y);
    __nv_bfloat162 l23 = __floats2bfloat162_rn(v.z - f23.x, v.w - f23.y);
    ((__nv_bfloat162*)hi)[2*i]   = h01;
    ((__nv_bfloat162*)hi)[2*i+1] = h23;
    ((__nv_bfloat162*)lo)[2*i]   = l01;
    ((__nv_bfloat162*)lo)[2*i+1] = l23;
}

// ===========================================================================
// Split-bf16 mma.sync GEMM v2: C[M,N] = (Ah+Al)[M,K] @ (Bh+Bl)[N,K]^T
// 128x128 tile, BK=32, 256 threads (8 warps 2x4, warp tile 64x32).
// cp.async 2-stage pipeline, ldmatrix.x4 fragment loads.
// EPI 0: fp32 C.  EPI 1: bf16 hi/lo C.
// ===========================================================================
#define LDA     40                      // bf16 elements per smem row
#define TILE_E  (128*LDA)               // elements per tile
#define TILE_BY (TILE_E*2)              // bytes per tile (10240)
#define STAGE_BY (4*TILE_BY)            // Ah, Al, Bh, Bl  (40960)
#define GEMM_SMEM (2*STAGE_BY)          // 81920

__device__ __forceinline__ void load_stage_cp(uint32_t sb,
                                              const __nv_bfloat16* __restrict__ Ah,
                                              const __nv_bfloat16* __restrict__ Al,
                                              const __nv_bfloat16* __restrict__ Bh,
                                              const __nv_bfloat16* __restrict__ Bl,
                                              int m0, int n0, int K, int k0, int tid) {
    const __nv_bfloat16* gp[4] = {Ah, Al, Bh, Bl};
    const int r0[4] = {m0, m0, n0, n0};
#pragma unroll
    for (int tIdx = 0; tIdx < 4; tIdx++) {
#pragma unroll
        for (int i = 0; i < 2; i++) {
            int u  = i * 256 + tid;          // 0..511
            int r  = u >> 2;                 // 0..127
            int cb = (u & 3) * 8;            // 0,8,16,24
            cpa16(sb + tIdx*TILE_BY + (r*LDA + cb)*2,
                  gp[tIdx] + (size_t)(r0[tIdx] + r) * K + k0 + cb);
        }
    }
}

template <int EPI>
__global__ __launch_bounds__(256, 1) void gemm_mma2(
    const __nv_bfloat16* __restrict__ Ah, const __nv_bfloat16* __restrict__ Al,
    const __nv_bfloat16* __restrict__ Bh, const __nv_bfloat16* __restrict__ Bl,
    float* __restrict__ C,
    __nv_bfloat16* __restrict__ Ch, __nv_bfloat16* __restrict__ Cl,
    int M, int N, int K, float scale) {
    extern __shared__ __nv_bfloat16 smp[];
    const uint32_t sb0 = smem_u32(smp);

    const int tid  = threadIdx.x;
    const int lane = tid & 31;
    const int wid  = tid >> 5;
    const int wm   = wid & 1;
    const int wn   = wid >> 1;
    const int g    = lane >> 2;
    const int t    = lane & 3;
    const int m0   = blockIdx.y * 128;
    const int n0   = blockIdx.x * 128;

    // per-lane ldmatrix address components (bytes)
    const uint32_t aoff = (uint32_t)(((lane & 15) * LDA + ((lane >> 4) << 3)) * 2);
    const uint32_t boff = (uint32_t)((((lane & 7) + ((lane >> 4) << 3)) * LDA +
                                      (((lane >> 3) & 1) << 3)) * 2);

    float acc[4][4][4];
#pragma unroll
    for (int a = 0; a < 4; a++)
#pragma unroll
        for (int b = 0; b < 4; b++)
#pragma unroll
            for (int c = 0; c < 4; c++) acc[a][b][c] = 0.0f;

    const int NSTEP = K >> 5;   // BK=32

    load_stage_cp(sb0, Ah, Al, Bh, Bl, m0, n0, K, 0, tid);
    CPA_COMMIT();

    for (int i = 0; i < NSTEP; i++) {
        if (i + 1 < NSTEP) {
            load_stage_cp(sb0 + ((i + 1) & 1) * STAGE_BY, Ah, Al, Bh, Bl,
                          m0, n0, K, (i + 1) * 32, tid);
            CPA_COMMIT();
            CPA_WAIT_1();
        } else {
            CPA_WAIT_0();
        }
        __syncthreads();

        const uint32_t st = sb0 + (i & 1) * STAGE_BY;
        const uint32_t tAh = st;
        const uint32_t tAl = st + TILE_BY;
        const uint32_t tBh = st + 2*TILE_BY;
        const uint32_t tBl = st + 3*TILE_BY;

#pragma unroll
        for (int ks = 0; ks < 2; ks++) {
            const int kb = ks * 16;
            unsigned ah[4][4], al[4][4], bh[4][2], bl[4][2];
#pragma unroll
            for (int mt = 0; mt < 4; mt++) {
                uint32_t ra = (uint32_t)(((wm*64 + mt*16) * LDA + kb) * 2);
                LDM4(ah[mt][0], ah[mt][1], ah[mt][2], ah[mt][3], tAh + ra + aoff);
                LDM4(al[mt][0], al[mt][1], al[mt][2], al[mt][3], tAl + ra + aoff);
            }
#pragma unroll
            for (int ntp = 0; ntp < 2; ntp++) {
                uint32_t rb = (uint32_t)(((wn*32 + ntp*16) * LDA + kb) * 2);
                LDM4(bh[2*ntp][0], bh[2*ntp][1], bh[2*ntp+1][0], bh[2*ntp+1][1],
                     tBh + rb + boff);
                LDM4(bl[2*ntp][0], bl[2*ntp][1], bl[2*ntp+1][0], bl[2*ntp+1][1],
                     tBl + rb + boff);
            }
#pragma unroll
            for (int mt = 0; mt < 4; mt++)
#pragma unroll
                for (int nt = 0; nt < 4; nt++) {
                    mma_bf16(acc[mt][nt], ah[mt][0], ah[mt][1], ah[mt][2], ah[mt][3],
                             bh[nt][0], bh[nt][1]);
                    mma_bf16(acc[mt][nt], ah[mt][0], ah[mt][1], ah[mt][2], ah[mt][3],
                             bl[nt][0], bl[nt][1]);
                    mma_bf16(acc[mt][nt], al[mt][0], al[mt][1], al[mt][2], al[mt][3],
                             bh[nt][0], bh[nt][1]);
                }
        }
        __syncthreads();
    }

#pragma unroll
    for (int mt = 0; mt < 4; mt++)
#pragma unroll
        for (int nt = 0; nt < 4; nt++) {
            int r = m0 + wm * 64 + mt * 16 + g;
            int c = n0 + wn * 32 + nt * 8 + t * 2;
            if (EPI == 0) {
                *(float2*)&C[(size_t)r * N + c] =
                    make_float2(acc[mt][nt][0], acc[mt][nt][1]);
                *(float2*)&C[(size_t)(r + 8) * N + c] =
                    make_float2(acc[mt][nt][2], acc[mt][nt][3]);
            } else {
#pragma unroll
                for (int half = 0; half < 2; half++) {
                    float v0 = acc[mt][nt][2*half+0] * scale;
                    float v1 = acc[mt][nt][2*half+1] * scale;
                    __nv_bfloat162 h = __floats2bfloat162_rn(v0, v1);
                    float2 f = __bfloat1622float2(h);
                    __nv_bfloat162 l = __floats2bfloat162_rn(v0 - f.x, v1 - f.y);
                    size_t off = (size_t)(r + 8*half) * N + c;
                    *(unsigned*)&Ch[off] = *(unsigned*)&h;
                    *(unsigned*)&Cl[off] = *(unsigned*)&l;
                }
            }
        }
}

// ---------------------------------------------------------------------------
// Transpose V (reads from QKV buffer, V at column offset 2560, stride QKVW)
// ---------------------------------------------------------------------------
__global__ __launch_bounds__(128) void transpose_v(
    const __nv_bfloat16* __restrict__ Vh, const __nv_bfloat16* __restrict__ Vl,
    __nv_bfloat16* __restrict__ Vth, __nv_bfloat16* __restrict__ Vtl) {
    __shared__ __nv_bfloat16 sm[64*72];
    const int st  = blockIdx.x;
    const int kvh = blockIdx.y;
    const int b   = blockIdx.z;
    const int tid = threadIdx.x;

    const __nv_bfloat16* src[2] = {Vh, Vl};
    __nv_bfloat16*       dst[2] = {Vth, Vtl};

#pragma unroll
    for (int a = 0; a < 2; a++) {
        __syncthreads();
#pragma unroll
        for (int i = 0; i < 4; i++) {
            int u = i*128 + tid;
            int r = u >> 3, c8 = u & 7;
            uint4 v = *(const uint4*)&src[a][((size_t)(b*SEQ + st*64 + r))*QKVW
                                             + (HIDDEN + KVDIM) + kvh*HD + c8*8];
            *(uint4*)&sm[r*72 + c8*8] = v;
        }
        __syncthreads();
#pragma unroll
        for (int i = 0; i < 4; i++) {
            int u = i*128 + tid;
            int d = u >> 3, t8 = (u & 7) * 8;
            __nv_bfloat16 tmp[8];
#pragma unroll
            for (int j = 0; j < 8; j++) tmp[j] = sm[(t8+j)*72 + d];
            *(uint4*)&dst[a][((size_t)((b*NKV + kvh)*HD + d))*SEQ + st*64 + t8] = *(uint4*)tmp;
        }
    }
}

// ---------------------------------------------------------------------------
// mma.sync flash attention. Q at col 0, K at col 2048 of QKV buffer.
// Scale 1/8 applied to S post-MMA.
// ---------------------------------------------------------------------------
#define LK 72

__global__ __launch_bounds__(128) void flash_mma(
    const __nv_bfloat16* __restrict__ QKVh, const __nv_bfloat16* __restrict__ QKVl,
    const __nv_bfloat16* __restrict__ Vth, const __nv_bfloat16* __restrict__ Vtl,
    __nv_bfloat16* __restrict__ Oh, __nv_bfloat16* __restrict__ Ol) {

    __shared__ __nv_bfloat16 sKh[64*LK], sKl[64*LK], sVh[64*LK], sVl[64*LK];

    const int qb  = blockIdx.x;
    const int h   = blockIdx.y;
    const int b   = blockIdx.z;
    const int kvh = h >> 2;

    const int tid  = threadIdx.x;
    const int wid  = tid >> 5;
    const int lane = tid & 31;
    const int g    = lane >> 2;
    const int t    = lane & 3;

    unsigned qh[4][4], ql[4][4];
    {
        const size_t row0 = (size_t)(b*SEQ + qb*64 + wid*16 + g) * QKVW + h*HD;
        const size_t row1 = row0 + (size_t)8 * QKVW;
#pragma unroll
        for (int ks = 0; ks < 4; ks++) {
            int c = ks*16 + t*2;
            qh[ks][0] = *(const unsigned*)&QKVh[row0 + c];
            qh[ks][1] = *(const unsigned*)&QKVh[row1 + c];
            qh[ks][2] = *(const unsigned*)&QKVh[row0 + c + 8];
            qh[ks][3] = *(const unsigned*)&QKVh[row1 + c + 8];
            ql[ks][0] = *(const unsigned*)&QKVl[row0 + c];
            ql[ks][1] = *(const unsigned*)&QKVl[row1 + c];
            ql[ks][2] = *(const unsigned*)&QKVl[row0 + c + 8];
            ql[ks][3] = *(const unsigned*)&QKVl[row1 + c + 8];
        }
    }

    float o[8][4];
#pragma unroll
    for (int j = 0; j < 8; j++)
#pragma unroll
        for (int c = 0; c < 4; c++) o[j][c] = 0.0f;
    float m0 = -1e30f, m1 = -1e30f, l0 = 0.0f, l1 = 0.0f;

    for (int kb = 0; kb <= qb; kb++) {
        __syncthreads();
        {
            const size_t kbase = (size_t)(b*SEQ + kb*64) * QKVW + HIDDEN + kvh*HD;
            const size_t vbase = (size_t)((b*NKV + kvh)*HD) * SEQ + kb*64;
#pragma unroll
            for (int i = 0; i < 4; i++) {
                int u = i*128 + tid;
                int r = u >> 3, c8 = (u & 7) * 8;
                *(uint4*)&sKh[r*LK + c8] = *(const uint4*)&QKVh[kbase + (size_t)r*QKVW + c8];
                *(uint4*)&sKl[r*LK + c8] = *(const uint4*)&QKVl[kbase + (size_t)r*QKVW + c8];
                *(uint4*)&sVh[r*LK + c8] = *(const uint4*)&Vth[vbase + (size_t)r*SEQ + c8];
                *(uint4*)&sVl[r*LK + c8] = *(const uint4*)&Vtl[vbase + (size_t)r*SEQ + c8];
            }
        }
        __syncthreads();

        float s[8][4];
#pragma unroll
        for (int j = 0; j < 8; j++) {
            s[j][0] = 0.0f; s[j][1] = 0.0f; s[j][2] = 0.0f; s[j][3] = 0.0f;
            const int rb = (8*j + g)*LK + t*2;
#pragma unroll
            for (int ks = 0; ks < 4; ks++) {
                unsigned bh0 = *(const unsigned*)&sKh[rb + ks*16];
                unsigned bh1 = *(const unsigned*)&sKh[rb + ks*16 + 8];
                unsigned bl0 = *(const unsigned*)&sKl[rb + ks*16];
                unsigned bl1 = *(const unsigned*)&sKl[rb + ks*16 + 8];
                mma_bf16(s[j], qh[ks][0], qh[ks][1], qh[ks][2], qh[ks][3], bh0, bh1);
                mma_bf16(s[j], qh[ks][0], qh[ks][1], qh[ks][2], qh[ks][3], bl0, bl1);
                mma_bf16(s[j], ql[ks][0], ql[ks][1], ql[ks][2], ql[ks][3], bh0, bh1);
            }
#pragma unroll
            for (int c = 0; c < 4; c++) s[j][c] *= 0.125f;
        }

        if (kb == qb) {
            const int r0 = wid*16 + g, r1 = r0 + 8;
#pragma unroll
            for (int j = 0; j < 8; j++) {
                int c0 = 8*j + t*2, c1 = c0 + 1;
                if (c0 > r0) s[j][0] = -1e30f;
                if (c1 > r0) s[j][1] = -1e30f;
                if (c0 > r1) s[j][2] = -1e30f;
                if (c1 > r1) s[j][3] = -1e30f;
            }
        }

        float mx0 = -1e30f, mx1 = -1e30f;
#pragma unroll
        for (int j = 0; j < 8; j++) {
            mx0 = fmaxf(mx0, fmaxf(s[j][0], s[j][1]));
            mx1 = fmaxf(mx1, fmaxf(s[j][2], s[j][3]));
        }
        mx0 = fmaxf(mx0, __shfl_xor_sync(0xffffffffu, mx0, 1));
        mx0 = fmaxf(mx0, __shfl_xor_sync(0xffffffffu, mx0, 2));
        mx1 = fmaxf(mx1, __shfl_xor_sync(0xffffffffu, mx1, 1));
        mx1 = fmaxf(mx1, __shfl_xor_sync(0xffffffffu, mx1, 2));
        float mn0 = fmaxf(m0, mx0), mn1 = fmaxf(m1, mx1);
        float al0 = __expf(m0 - mn0), al1 = __expf(m1 - mn1);

        float rs0 = 0.0f, rs1 = 0.0f;
#pragma unroll
        for (int j = 0; j < 8; j++) {
            s[j][0] = __expf(s[j][0] - mn0);
            s[j][1] = __expf(s[j][1] - mn0);
            s[j][2] = __expf(s[j][2] - mn1);
            s[j][3] = __expf(s[j][3] - mn1);
            rs0 += s[j][0] + s[j][1];
            rs1 += s[j][2] + s[j][3];
        }
        rs0 += __shfl_xor_sync(0xffffffffu, rs0, 1);
        rs0 += __shfl_xor_sync(0xffffffffu, rs0, 2);
        rs1 += __shfl_xor_sync(0xffffffffu, rs1, 1);
        rs1 += __shfl_xor_sync(0xffffffffu, rs1, 2);
        l0 = l0 * al0 + rs0;  m0 = mn0;
        l1 = l1 * al1 + rs1;  m1 = mn1;

#pragma unroll
        for (int j = 0; j < 8; j++) {
            o[j][0] *= al0; o[j][1] *= al0;
            o[j][2] *= al1; o[j][3] *= al1;
        }

        unsigned ph[4][4], pl[4][4];
#pragma unroll
        for (int ks = 0; ks < 4; ks++) {
            __nv_bfloat162 h0 = __floats2bfloat162_rn(s[2*ks][0],   s[2*ks][1]);
            __nv_bfloat162 h1 = __floats2bfloat162_rn(s[2*ks][2],   s[2*ks][3]);
            __nv_bfloat162 h2 = __floats2bfloat162_rn(s[2*ks+1][0], s[2*ks+1][1]);
            __nv_bfloat162 h3 = __floats2bfloat162_rn(s[2*ks+1][2], s[2*ks+1][3]);
            float2 f0 = __bfloat1622float2(h0);
            float2 f1 = __bfloat1622float2(h1);
            float2 f2 = __bfloat1622float2(h2);
            float2 f3 = __bfloat1622float2(h3);
            __nv_bfloat162 L0 = __floats2bfloat162_rn(s[2*ks][0]-f0.x,   s[2*ks][1]-f0.y);
            __nv_bfloat162 L1 = __floats2bfloat162_rn(s[2*ks][2]-f1.x,   s[2*ks][3]-f1.y);
            __nv_bfloat162 L2 = __floats2bfloat162_rn(s[2*ks+1][0]-f2.x, s[2*ks+1][1]-f2.y);
            __nv_bfloat162 L3 = __floats2bfloat162_rn(s[2*ks+1][2]-f3.x, s[2*ks+1][3]-f3.y);
            ph[ks][0] = *(unsigned*)&h0; ph[ks][1] = *(unsigned*)&h1;
            ph[ks][2] = *(unsigned*)&h2; ph[ks][3] = *(unsigned*)&h3;
            pl[ks][0] = *(unsigned*)&L0; pl[ks][1] = *(unsigned*)&L1;
            pl[ks][2] = *(unsigned*)&L2; pl[ks][3] = *(unsigned*)&L3;
        }

#pragma unroll
        for (int j = 0; j < 8; j++) {
            const int rb = (8*j + g)*LK + t*2;
#pragma unroll
            for (int ks = 0; ks < 4; ks++) {
                unsigned bh0 = *(const unsigned*)&sVh[rb + ks*16];
                unsigned bh1 = *(const unsigned*)&sVh[rb + ks*16 + 8];
                unsigned bl0 = *(const unsigned*)&sVl[rb + ks*16];
                unsigned bl1 = *(const unsigned*)&sVl[rb + ks*16 + 8];
                mma_bf16(o[j], ph[ks][0], ph[ks][1], ph[ks][2], ph[ks][3], bh0, bh1);
                mma_bf16(o[j], ph[ks][0], ph[ks][1], ph[ks][2], ph[ks][3], bl0, bl1);
                mma_bf16(o[j], pl[ks][0], pl[ks][1], pl[ks][2], pl[ks][3], bh0, bh1);
            }
        }
    }

    const float inv0 = 1.0f / l0, inv1 = 1.0f / l1;
    const size_t row0 = (size_t)(b*SEQ + qb*64 + wid*16 + g) * HIDDEN + h*HD;
    const size_t row1 = row0 + (size_t)8 * HIDDEN;
#pragma unroll
    for (int j = 0; j < 8; j++) {
        int c = 8*j + t*2;
        float v0 = o[j][0]*inv0, v1 = o[j][1]*inv0;
        float v2 = o[j][2]*inv1, v3 = o[j][3]*inv1;
        __nv_bfloat162 h01 = __floats2bfloat162_rn(v0, v1);
        __nv_bfloat162 h23 = __floats2bfloat162_rn(v2, v3);
        float2 f01 = __bfloat1622float2(h01);
        float2 f23 = __bfloat1622float2(h23);
        __nv_bfloat162 l01 = __floats2bfloat162_rn(v0 - f01.x, v1 - f01.y);
        __nv_bfloat162 l23 = __floats2bfloat162_rn(v2 - f23.x, v3 - f23.y);
        *(unsigned*)&Oh[row0 + c] = *(unsigned*)&h01;
        *(unsigned*)&Oh[row1 + c] = *(unsigned*)&h23;
        *(unsigned*)&Ol[row0 + c] = *(unsigned*)&l01;
        *(unsigned*)&Ol[row1 + c] = *(unsigned*)&l23;
    }
}

// ---------------------------------------------------------------------------
extern "C" void kernel_launch(void* const* d_in, const int* in_sizes, int n_in,
                              void* d_out, int out_size) {
    const float* x  = (const float*)d_in[0];
    const float* Wq = (const float*)d_in[1];
    const float* Wk = (const float*)d_in[2];
    const float* Wv = (const float*)d_in[3];
    const float* Wo = (const float*)d_in[4];
    float* out = (float*)d_out;

    __nv_bfloat16 *xh, *xl, *wh, *wl, *woh, *wol;
    __nv_bfloat16 *qkvh, *qkvl, *vth, *vtl, *aoh, *aol;
    cudaGetSymbolAddress((void**)&xh,   g_xh);   cudaGetSymbolAddress((void**)&xl,   g_xl);
    cudaGetSymbolAddress((void**)&wh,   g_Wh);   cudaGetSymbolAddress((void**)&wl,   g_Wl);
    cudaGetSymbolAddress((void**)&woh,  g_Woh);  cudaGetSymbolAddress((void**)&wol,  g_Wol);
    cudaGetSymbolAddress((void**)&qkvh, g_QKVh); cudaGetSymbolAddress((void**)&qkvl, g_QKVl);
    cudaGetSymbolAddress((void**)&vth,  g_Vth);  cudaGetSymbolAddress((void**)&vtl,  g_Vtl);
    cudaGetSymbolAddress((void**)&aoh,  g_AOh);  cudaGetSymbolAddress((void**)&aol,  g_AOl);

    const int M = MTOK;

    // splits (Wq/Wk/Wv into concatenated buffer)
    {
        int n4;
        n4 = M*HIDDEN/4;      split_f32<<<(n4+255)/256, 256>>>(x,  xh, xl, n4);
        n4 = HIDDEN*HIDDEN/4; split_f32<<<(n4+255)/256, 256>>>(Wq, wh, wl, n4);
        n4 = KVDIM*HIDDEN/4;
        split_f32<<<(n4+255)/256, 256>>>(Wk, wh + (size_t)HIDDEN*HIDDEN,
                                             wl + (size_t)HIDDEN*HIDDEN, n4);
        split_f32<<<(n4+255)/256, 256>>>(Wv, wh + (size_t)(HIDDEN+KVDIM)*HIDDEN,
                                             wl + (size_t)(HIDDEN+KVDIM)*HIDDEN, n4);
        n4 = HIDDEN*HIDDEN/4; split_f32<<<(n4+255)/256, 256>>>(Wo, woh, wol, n4);
    }

    cudaFuncSetAttribute(gemm_mma2<0>, cudaFuncAttributeMaxDynamicSharedMemorySize, GEMM_SMEM);
    cudaFuncSetAttribute(gemm_mma2<1>, cudaFuncAttributeMaxDynamicSharedMemorySize, GEMM_SMEM);

    // fused QKV projection -> bf16 hi/lo
    {
        dim3 blk(256);
        dim3 gq(QKVW/128, M/128);
        gemm_mma2<1><<<gq, blk, GEMM_SMEM>>>(xh, xl, wh, wl, nullptr, qkvh, qkvl,
                                             M, QKVW, HIDDEN, 1.0f);
    }

    // V transpose
    {
        dim3 grid(SEQ/64, NKV, BATCH);
        transpose_v<<<grid, 128>>>(qkvh, qkvl, vth, vtl);
    }

    // flash attention
    {
        dim3 grid(SEQ/64, NH, BATCH);
        flash_mma<<<grid, 128>>>(qkvh, qkvl, vth, vtl, aoh, aol);
    }

    // output projection (fp32 out)
    {
        dim3 blk(256);
        dim3 go(HIDDEN/128, M/128);
        gemm_mma2<0><<<go, blk, GEMM_SMEM>>>(aoh, aol, woh, wol, out, nullptr, nullptr,
                                             M, HIDDEN, HIDDEN, 1.0f);
    }
}

// round 6
// speedup vs baseline: 6.6688x; 2.7252x over previous
#include <cuda_runtime.h>
#include <cuda_fp16.h>
#include <math.h>
#include <stdint.h>

#define BATCH  2
#define SEQ    2048
#define HIDDEN 2048
#define NH     32
#define NKV    8
#define HD     64
#define KVDIM  (NKV*HD)    // 512
#define MTOK   (BATCH*SEQ) // 4096
#define QKVW   (HIDDEN + 2*KVDIM)  // 3072

// ------------------------- device scratch (no allocs) ----------------------
__device__ __half g_x  [MTOK*HIDDEN];
__device__ __half g_W  [QKVW*HIDDEN];      // Wq | Wk | Wv rows concat
__device__ __half g_Wo [HIDDEN*HIDDEN];
__device__ __half g_QKV[MTOK*QKVW];        // [token][ Q(2048) K(512) V(512) ]
__device__ __half g_Vt [BATCH*NKV*HD*SEQ]; // [(b*8+kvh)*64+d][token]
__device__ __half g_AO [MTOK*HIDDEN];

// ============================ helpers ======================================
__device__ __forceinline__ uint32_t smem_u32(const void* p) {
    uint32_t a;
    asm("{ .reg .u64 t; cvta.to.shared.u64 t, %1; cvt.u32.u64 %0, t; }"
        : "=r"(a) : "l"(p));
    return a;
}
__device__ __forceinline__ void cpa16(uint32_t dst, const void* src) {
    asm volatile("cp.async.cg.shared.global [%0], [%1], 16;\n" :: "r"(dst), "l"(src));
}
#define CPA_COMMIT() asm volatile("cp.async.commit_group;\n" ::: "memory")
#define CPA_WAIT_1() asm volatile("cp.async.wait_group 1;\n" ::: "memory")
#define CPA_WAIT_0() asm volatile("cp.async.wait_group 0;\n" ::: "memory")

__device__ __forceinline__ void mma_f16(float c[4],
                                        unsigned a0, unsigned a1, unsigned a2, unsigned a3,
                                        unsigned b0, unsigned b1) {
    asm volatile(
        "mma.sync.aligned.m16n8k16.row.col.f32.f16.f16.f32 "
        "{%0,%1,%2,%3}, {%4,%5,%6,%7}, {%8,%9}, {%0,%1,%2,%3};\n"
        : "+f"(c[0]), "+f"(c[1]), "+f"(c[2]), "+f"(c[3])
        : "r"(a0), "r"(a1), "r"(a2), "r"(a3), "r"(b0), "r"(b1));
}
#define LDM4(r0, r1, r2, r3, a) \
    asm volatile("ldmatrix.sync.aligned.m8n8.x4.shared.b16 {%0,%1,%2,%3}, [%4];" \
        : "=r"(r0), "=r"(r1), "=r"(r2), "=r"(r3) : "r"(a))

// ---------------------------------------------------------------------------
// fp32 -> fp16 convert, 4 elements/thread
// ---------------------------------------------------------------------------
__global__ void conv_f16(const float* __restrict__ s, __half* __restrict__ d, int n4) {
    int i = blockIdx.x * blockDim.x + threadIdx.x;
    if (i >= n4) return;
    float4 v = ((const float4*)s)[i];
    __half2 a = __floats2half2_rn(v.x, v.y);
    __half2 b = __floats2half2_rn(v.z, v.w);
    ((__half2*)d)[2*i]   = a;
    ((__half2*)d)[2*i+1] = b;
}

// ===========================================================================
// fp16 mma.sync GEMM: C[M,N] = A[M,K] @ B[N,K]^T
// 128x128 tile, BK=64, 256 threads (8 warps 2x4, warp tile 64x32).
// cp.async 2-stage pipeline, ldmatrix.x4 loads, 2 CTAs/SM.
// EPI 0: fp32 C.  EPI 1: fp16 C, first scale_cols columns scaled.
// ===========================================================================
#define LDA      72                     // fp16 elements per smem row (64 + 8 pad)
#define TILE_BY  (128*LDA*2)            // 18432 B
#define STAGE_BY (2*TILE_BY)            // 36864 B (A, B)
#define GEMM_SMEM (2*STAGE_BY)          // 73728 B

__device__ __forceinline__ void load_stage(uint32_t sb,
                                           const __half* __restrict__ A,
                                           const __half* __restrict__ B,
                                           int m0, int n0, int K, int k0, int tid) {
    const __half* gp[2] = {A, B};
    const int r0[2] = {m0, n0};
#pragma unroll
    for (int tIdx = 0; tIdx < 2; tIdx++) {
#pragma unroll
        for (int i = 0; i < 4; i++) {
            int u  = i * 256 + tid;          // 0..1023
            int r  = u >> 3;                 // 0..127
            int c8 = (u & 7) * 8;            // 0..56 step 8
            cpa16(sb + tIdx*TILE_BY + (r*LDA + c8)*2,
                  gp[tIdx] + (size_t)(r0[tIdx] + r) * K + k0 + c8);
        }
    }
}

template <int EPI>
__global__ __launch_bounds__(256, 2) void gemm_f16(
    const __half* __restrict__ A, const __half* __restrict__ B,
    float* __restrict__ C, __half* __restrict__ Ch,
    int M, int N, int K, int scale_cols, float scale) {
    extern __shared__ __half smp[];
    const uint32_t sb0 = smem_u32(smp);

    const int tid  = threadIdx.x;
    const int lane = tid & 31;
    const int wid  = tid >> 5;
    const int wm   = wid & 1;
    const int wn   = wid >> 1;
    const int g    = lane >> 2;
    const int t    = lane & 3;
    const int m0   = blockIdx.y * 128;
    const int n0   = blockIdx.x * 128;

    const uint32_t aoff = (uint32_t)(((lane & 15) * LDA + ((lane >> 4) << 3)) * 2);
    const uint32_t boff = (uint32_t)((((lane & 7) + ((lane >> 4) << 3)) * LDA +
                                      (((lane >> 3) & 1) << 3)) * 2);

    float acc[4][4][4];
#pragma unroll
    for (int a = 0; a < 4; a++)
#pragma unroll
        for (int b = 0; b < 4; b++)
#pragma unroll
            for (int c = 0; c < 4; c++) acc[a][b][c] = 0.0f;

    const int NSTEP = K >> 6;   // BK=64

    load_stage(sb0, A, B, m0, n0, K, 0, tid);
    CPA_COMMIT();

    for (int i = 0; i < NSTEP; i++) {
        if (i + 1 < NSTEP) {
            load_stage(sb0 + ((i + 1) & 1) * STAGE_BY, A, B, m0, n0, K, (i + 1) * 64, tid);
            CPA_COMMIT();
            CPA_WAIT_1();
        } else {
            CPA_WAIT_0();
        }
        __syncthreads();

        const uint32_t st = sb0 + (i & 1) * STAGE_BY;
        const uint32_t tA = st;
        const uint32_t tB = st + TILE_BY;

#pragma unroll
        for (int ks = 0; ks < 4; ks++) {
            const int kb = ks * 16;
            unsigned ah[4][4], bh[4][2];
#pragma unroll
            for (int mt = 0; mt < 4; mt++) {
                uint32_t ra = (uint32_t)(((wm*64 + mt*16) * LDA + kb) * 2);
                LDM4(ah[mt][0], ah[mt][1], ah[mt][2], ah[mt][3], tA + ra + aoff);
            }
#pragma unroll
            for (int ntp = 0; ntp < 2; ntp++) {
                uint32_t rb = (uint32_t)(((wn*32 + ntp*16) * LDA + kb) * 2);
                LDM4(bh[2*ntp][0], bh[2*ntp][1], bh[2*ntp+1][0], bh[2*ntp+1][1],
                     tB + rb + boff);
            }
#pragma unroll
            for (int mt = 0; mt < 4; mt++)
#pragma unroll
                for (int nt = 0; nt < 4; nt++)
                    mma_f16(acc[mt][nt], ah[mt][0], ah[mt][1], ah[mt][2], ah[mt][3],
                            bh[nt][0], bh[nt][1]);
        }
        __syncthreads();
    }

    const float sc = (EPI == 1 && n0 < scale_cols) ? scale : 1.0f;
#pragma unroll
    for (int mt = 0; mt < 4; mt++)
#pragma unroll
        for (int nt = 0; nt < 4; nt++) {
            int r = m0 + wm * 64 + mt * 16 + g;
            int c = n0 + wn * 32 + nt * 8 + t * 2;
            if (EPI == 0) {
                *(float2*)&C[(size_t)r * N + c] =
                    make_float2(acc[mt][nt][0], acc[mt][nt][1]);
                *(float2*)&C[(size_t)(r + 8) * N + c] =
                    make_float2(acc[mt][nt][2], acc[mt][nt][3]);
            } else {
                __half2 h0 = __floats2half2_rn(acc[mt][nt][0]*sc, acc[mt][nt][1]*sc);
                __half2 h1 = __floats2half2_rn(acc[mt][nt][2]*sc, acc[mt][nt][3]*sc);
                *(unsigned*)&Ch[(size_t)r * N + c]       = *(unsigned*)&h0;
                *(unsigned*)&Ch[(size_t)(r + 8) * N + c] = *(unsigned*)&h1;
            }
        }
}

// ---------------------------------------------------------------------------
// Transpose V: QKV[token][2560 + kvh*64 + d] -> Vt[(b*8+kvh)*64+d][token]
// ---------------------------------------------------------------------------
__global__ __launch_bounds__(128) void transpose_v(
    const __half* __restrict__ QKV, __half* __restrict__ Vt) {
    __shared__ __half sm[64*72];
    const int st  = blockIdx.x;
    const int kvh = blockIdx.y;
    const int b   = blockIdx.z;
    const int tid = threadIdx.x;

#pragma unroll
    for (int i = 0; i < 4; i++) {
        int u = i*128 + tid;
        int r = u >> 3, c8 = u & 7;
        uint4 v = *(const uint4*)&QKV[((size_t)(b*SEQ + st*64 + r))*QKVW
                                      + (HIDDEN + KVDIM) + kvh*HD + c8*8];
        *(uint4*)&sm[r*72 + c8*8] = v;
    }
    __syncthreads();
#pragma unroll
    for (int i = 0; i < 4; i++) {
        int u = i*128 + tid;
        int d = u >> 3, t8 = (u & 7) * 8;
        __half tmp[8];
#pragma unroll
        for (int j = 0; j < 8; j++) tmp[j] = sm[(t8+j)*72 + d];
        *(uint4*)&Vt[((size_t)((b*NKV + kvh)*HD + d))*SEQ + st*64 + t8] = *(uint4*)tmp;
    }
}

// ---------------------------------------------------------------------------
// fp16 mma.sync flash attention (causal, GQA). Q pre-scaled by 1/8.
// CTA 128 thr / 4 warps, q-tile 64, k-tile 64.
// ---------------------------------------------------------------------------
#define LK 72

__global__ __launch_bounds__(128) void flash_mma(
    const __half* __restrict__ QKV, const __half* __restrict__ Vt,
    __half* __restrict__ O) {

    __shared__ __half sK[64*LK], sV[64*LK];

    const int qb  = blockIdx.x;
    const int h   = blockIdx.y;
    const int b   = blockIdx.z;
    const int kvh = h >> 2;

    const int tid  = threadIdx.x;
    const int wid  = tid >> 5;
    const int lane = tid & 31;
    const int g    = lane >> 2;
    const int t    = lane & 3;

    unsigned qf[4][4];
    {
        const size_t row0 = (size_t)(b*SEQ + qb*64 + wid*16 + g) * QKVW + h*HD;
        const size_t row1 = row0 + (size_t)8 * QKVW;
#pragma unroll
        for (int ks = 0; ks < 4; ks++) {
            int c = ks*16 + t*2;
            qf[ks][0] = *(const unsigned*)&QKV[row0 + c];
            qf[ks][1] = *(const unsigned*)&QKV[row1 + c];
            qf[ks][2] = *(const unsigned*)&QKV[row0 + c + 8];
            qf[ks][3] = *(const unsigned*)&QKV[row1 + c + 8];
        }
    }

    float o[8][4];
#pragma unroll
    for (int j = 0; j < 8; j++)
#pragma unroll
        for (int c = 0; c < 4; c++) o[j][c] = 0.0f;
    float m0 = -1e30f, m1 = -1e30f, l0 = 0.0f, l1 = 0.0f;

    for (int kb = 0; kb <= qb; kb++) {
        __syncthreads();
        {
            const size_t kbase = (size_t)(b*SEQ + kb*64) * QKVW + HIDDEN + kvh*HD;
            const size_t vbase = (size_t)((b*NKV + kvh)*HD) * SEQ + kb*64;
#pragma unroll
            for (int i = 0; i < 4; i++) {
                int u = i*128 + tid;
                int r = u >> 3, c8 = (u & 7) * 8;
                *(uint4*)&sK[r*LK + c8] = *(const uint4*)&QKV[kbase + (size_t)r*QKVW + c8];
                *(uint4*)&sV[r*LK + c8] = *(const uint4*)&Vt[vbase + (size_t)r*SEQ + c8];
            }
        }
        __syncthreads();

        float s[8][4];
#pragma unroll
        for (int j = 0; j < 8; j++) {
            s[j][0] = 0.0f; s[j][1] = 0.0f; s[j][2] = 0.0f; s[j][3] = 0.0f;
            const int rb = (8*j + g)*LK + t*2;
#pragma unroll
            for (int ks = 0; ks < 4; ks++) {
                unsigned b0 = *(const unsigned*)&sK[rb + ks*16];
                unsigned b1 = *(const unsigned*)&sK[rb + ks*16 + 8];
                mma_f16(s[j], qf[ks][0], qf[ks][1], qf[ks][2], qf[ks][3], b0, b1);
            }
        }

        if (kb == qb) {
            const int r0 = wid*16 + g, r1 = r0 + 8;
#pragma unroll
            for (int j = 0; j < 8; j++) {
                int c0 = 8*j + t*2, c1 = c0 + 1;
                if (c0 > r0) s[j][0] = -1e30f;
                if (c1 > r0) s[j][1] = -1e30f;
                if (c0 > r1) s[j][2] = -1e30f;
                if (c1 > r1) s[j][3] = -1e30f;
            }
        }

        float mx0 = -1e30f, mx1 = -1e30f;
#pragma unroll
        for (int j = 0; j < 8; j++) {
            mx0 = fmaxf(mx0, fmaxf(s[j][0], s[j][1]));
            mx1 = fmaxf(mx1, fmaxf(s[j][2], s[j][3]));
        }
        mx0 = fmaxf(mx0, __shfl_xor_sync(0xffffffffu, mx0, 1));
        mx0 = fmaxf(mx0, __shfl_xor_sync(0xffffffffu, mx0, 2));
        mx1 = fmaxf(mx1, __shfl_xor_sync(0xffffffffu, mx1, 1));
        mx1 = fmaxf(mx1, __shfl_xor_sync(0xffffffffu, mx1, 2));
        float mn0 = fmaxf(m0, mx0), mn1 = fmaxf(m1, mx1);
        float al0 = __expf(m0 - mn0), al1 = __expf(m1 - mn1);

        float rs0 = 0.0f, rs1 = 0.0f;
#pragma unroll
        for (int j = 0; j < 8; j++) {
            s[j][0] = __expf(s[j][0] - mn0);
            s[j][1] = __expf(s[j][1] - mn0);
            s[j][2] = __expf(s[j][2] - mn1);
            s[j][3] = __expf(s[j][3] - mn1);
            rs0 += s[j][0] + s[j][1];
            rs1 += s[j][2] + s[j][3];
        }
        rs0 += __shfl_xor_sync(0xffffffffu, rs0, 1);
        rs0 += __shfl_xor_sync(0xffffffffu, rs0, 2);
        rs1 += __shfl_xor_sync(0xffffffffu, rs1, 1);
        rs1 += __shfl_xor_sync(0xffffffffu, rs1, 2);
        l0 = l0 * al0 + rs0;  m0 = mn0;
        l1 = l1 * al1 + rs1;  m1 = mn1;

#pragma unroll
        for (int j = 0; j < 8; j++) {
            o[j][0] *= al0; o[j][1] *= al0;
            o[j][2] *= al1; o[j][3] *= al1;
        }

        unsigned pf[4][4];
#pragma unroll
        for (int ks = 0; ks < 4; ks++) {
            __half2 h0 = __floats2half2_rn(s[2*ks][0],   s[2*ks][1]);
            __half2 h1 = __floats2half2_rn(s[2*ks][2],   s[2*ks][3]);
            __half2 h2 = __floats2half2_rn(s[2*ks+1][0], s[2*ks+1][1]);
            __half2 h3 = __floats2half2_rn(s[2*ks+1][2], s[2*ks+1][3]);
            pf[ks][0] = *(unsigned*)&h0; pf[ks][1] = *(unsigned*)&h1;
            pf[ks][2] = *(unsigned*)&h2; pf[ks][3] = *(unsigned*)&h3;
        }

#pragma unroll
        for (int j = 0; j < 8; j++) {
            const int rb = (8*j + g)*LK + t*2;
#pragma unroll
            for (int ks = 0; ks < 4; ks++) {
                unsigned b0 = *(const unsigned*)&sV[rb + ks*16];
                unsigned b1 = *(const unsigned*)&sV[rb + ks*16 + 8];
                mma_f16(o[j], pf[ks][0], pf[ks][1], pf[ks][2], pf[ks][3], b0, b1);
            }
        }
    }

    const float inv0 = 1.0f / l0, inv1 = 1.0f / l1;
    const size_t row0 = (size_t)(b*SEQ + qb*64 + wid*16 + g) * HIDDEN + h*HD;
    const size_t row1 = row0 + (size_t)8 * HIDDEN;
#pragma unroll
    for (int j = 0; j < 8; j++) {
        int c = 8*j + t*2;
        __half2 h0 = __floats2half2_rn(o[j][0]*inv0, o[j][1]*inv0);
        __half2 h1 = __floats2half2_rn(o[j][2]*inv1, o[j][3]*inv1);
        *(unsigned*)&O[row0 + c] = *(unsigned*)&h0;
        *(unsigned*)&O[row1 + c] = *(unsigned*)&h1;
    }
}

// ---------------------------------------------------------------------------
extern "C" void kernel_launch(void* const* d_in, const int* in_sizes, int n_in,
                              void* d_out, int out_size) {
    const float* x  = (const float*)d_in[0];
    const float* Wq = (const float*)d_in[1];
    const float* Wk = (const float*)d_in[2];
    const float* Wv = (const float*)d_in[3];
    const float* Wo = (const float*)d_in[4];
    float* out = (float*)d_out;

    __half *xp, *wp, *wop, *qkvp, *vtp, *aop;
    cudaGetSymbolAddress((void**)&xp,   g_x);
    cudaGetSymbolAddress((void**)&wp,   g_W);
    cudaGetSymbolAddress((void**)&wop,  g_Wo);
    cudaGetSymbolAddress((void**)&qkvp, g_QKV);
    cudaGetSymbolAddress((void**)&vtp,  g_Vt);
    cudaGetSymbolAddress((void**)&aop,  g_AO);

    const int M = MTOK;

    // fp32 -> fp16 converts (W q/k/v into concatenated buffer)
    {
        int n4;
        n4 = M*HIDDEN/4;      conv_f16<<<(n4+255)/256, 256>>>(x,  xp, n4);
        n4 = HIDDEN*HIDDEN/4; conv_f16<<<(n4+255)/256, 256>>>(Wq, wp, n4);
        n4 = KVDIM*HIDDEN/4;
        conv_f16<<<(n4+255)/256, 256>>>(Wk, wp + (size_t)HIDDEN*HIDDEN, n4);
        conv_f16<<<(n4+255)/256, 256>>>(Wv, wp + (size_t)(HIDDEN+KVDIM)*HIDDEN, n4);
        n4 = HIDDEN*HIDDEN/4; conv_f16<<<(n4+255)/256, 256>>>(Wo, wop, n4);
    }

    cudaFuncSetAttribute(gemm_f16<0>, cudaFuncAttributeMaxDynamicSharedMemorySize, GEMM_SMEM);
    cudaFuncSetAttribute(gemm_f16<1>, cudaFuncAttributeMaxDynamicSharedMemorySize, GEMM_SMEM);

    // fused QKV projection -> fp16 (Q columns scaled by 1/8)
    {
        dim3 blk(256);
        dim3 gq(QKVW/128, M/128);
        gemm_f16<1><<<gq, blk, GEMM_SMEM>>>(xp, wp, nullptr, qkvp,
                                            M, QKVW, HIDDEN, HIDDEN, 0.125f);
    }

    // V transpose
    {
        dim3 grid(SEQ/64, NKV, BATCH);
        transpose_v<<<grid, 128>>>(qkvp, vtp);
    }

    // flash attention
    {
        dim3 grid(SEQ/64, NH, BATCH);
        flash_mma<<<grid, 128>>>(qkvp, vtp, aop);
    }

    // output projection (fp32 out)
    {
        dim3 blk(256);
        dim3 go(HIDDEN/128, M/128);
        gemm_f16<0><<<go, blk, GEMM_SMEM>>>(aop, wop, out, nullptr,
                                            M, HIDDEN, HIDDEN, 0, 1.0f);
    }
}